// round 8
// baseline (speedup 1.0000x reference)
#include <cuda_runtime.h>
#include <cuda_bf16.h>
#include <math.h>
#include <stdint.h>

// ----- problem constants -----
#define E_TOTAL 800000
#define NN      50000
#define DIN     64
#define EIN     32
#define EMIN    160
#define HID     128
#define EOUT    64
#define NMIN    128
#define DOUT    64

#define TILE    128
#define NTILES  (E_TOTAL / TILE)   // 6250
#define GRID_P  148

#define TE      32
#define PITCH   34

// fragment-block layout: per (mt,kt) block of 132 floats (528B, 16B aligned)
#define FB      132
#define KT1     20      // layer-1 k-tiles
#define JT2     16      // layer-2 k-tiles (h)
#define MT      8       // m-tiles (128 rows / 16)

// ----- scratch -----
__device__ float g_logits[E_TOTAL];
__device__ float g_ex[E_TOTAL];
__device__ float g_m[NN];
__device__ float g_denom[NN];
__device__ float g_agg[(size_t)NN * EOUT];

// ----- smem layouts (bytes) -----
#define SM_X     0
#define X_BYTES  (MT * KT1 * FB * 4)       // 84480
#define SM_B1    X_BYTES                   // 81920 B
#define SM_B2    (SM_B1 + 81920)           // 32768 B (kernel E)
#define SM_BE1   (SM_B2 + 32768)
#define SM_BE2   (SM_BE1 + 512)
#define SMEM_E   (SM_BE2 + 256)            // 199936 B

#define SM_BA1   (SM_B1 + 81920)           // kernel A
#define SM_WA2   (SM_BA1 + 512)
#define SM_PART  (SM_WA2 + 512)
#define SMEM_A   (SM_PART + 1024)          // 168448 B

// ============================================================ helpers
union F2 { float2 f; unsigned long long u; };
__device__ __forceinline__ void fma2(F2& acc, F2 x, F2 w) {
    asm("fma.rn.f32x2 %0, %1, %2, %0;" : "+l"(acc.u) : "l"(x.u), "l"(w.u));
}
__device__ __forceinline__ void atomicMaxFloat(float* addr, float v) {
    if (v >= 0.0f) atomicMax((int*)addr, __float_as_int(v));
    else           atomicMin((unsigned int*)addr, __float_as_uint(v));
}
__device__ __forceinline__ uint32_t f2tf(float f) {
    uint32_t r; asm("cvt.rna.tf32.f32 %0, %1;" : "=r"(r) : "f"(f)); return r;
}
__device__ __forceinline__ float tfbits(float f) { return __uint_as_float(f2tf(f)); }

__device__ __forceinline__ void mma8(float* d, const uint32_t* a, uint32_t b0, uint32_t b1) {
    asm volatile(
        "mma.sync.aligned.m16n8k8.row.col.f32.tf32.tf32.f32 "
        "{%0,%1,%2,%3}, {%4,%5,%6,%7}, {%8,%9}, {%0,%1,%2,%3};"
        : "+f"(d[0]), "+f"(d[1]), "+f"(d[2]), "+f"(d[3])
        : "r"(a[0]), "r"(a[1]), "r"(a[2]), "r"(a[3]), "r"(b0), "r"(b1));
}

// gather one 128-edge tile into vectorized A-fragment blocks.
// Block (mt,kt) holds lane*16B: [a0,a1,a2,a3] with
//   a_reg = half + 2*thalf, element (row = g+8*half, col = tig+4*thalf).
__device__ __forceinline__ void gather_tile(
    float* sx, const float* __restrict__ nf, const float* __restrict__ ef,
    const int* __restrict__ src, const int* __restrict__ dst, int tile, int tid)
{
    const int e_loc = tid >> 1, kh = tid & 1;
    const int e = tile * TILE + e_loc;
    const int s = src[e], d = dst[e];
    const int mt = e_loc >> 4;
    const int rr = e_loc & 15;
    const int g = rr & 7, half = rr >> 3;
    const float4* nfs = (const float4*)nf + (size_t)s * 16;
    const float4* nfd = (const float4*)nf + (size_t)d * 16;
    const float4* efe = (const float4*)ef + (size_t)e * 8;
    #pragma unroll
    for (int j = 0; j < 20; j++) {
        float4 v;
        if (kh == 0) v = (j < 16) ? nfs[j] : nfd[j - 16];
        else         v = (j < 12) ? nfd[4 + j] : efe[j - 12];
        const int kt = kh * 10 + (j >> 1);
        float* base = sx + (mt * KT1 + kt) * FB + g * 16 + half + 2 * (j & 1);
        base[0]  = tfbits(v.x);
        base[4]  = tfbits(v.y);
        base[8]  = tfbits(v.z);
        base[12] = tfbits(v.w);
    }
}

// pack [K x N] row-major weight into paired B-fragment layout:
// float4 per lane per (kt, np) = [b(2np)0, b(2np)1, b(2np+1)0, b(2np+1)1]
__device__ __forceinline__ void pack_Bv(float* fb, const float* __restrict__ W,
                                        int K, int N, int tid, int nthr)
{
    const int NPB = N >> 4;
    for (int idx = tid; idx < K * N; idx += nthr) {
        const int k = idx / N, n = idx - k * N;
        const int lane = ((n & 7) << 2) + (k & 3);
        const int blk = (k >> 3) * NPB + (n >> 4);
        fb[(blk * 32 + lane) * 4 + ((n >> 3) & 1) * 2 + ((k >> 2) & 1)] = tfbits(W[idx]);
    }
}

// ============================================================
// K0: init scratch
// ============================================================
__global__ void init_kernel() {
    int idx = blockIdx.x * blockDim.x + threadIdx.x;
    g_agg[idx] = 0.0f;
    if (idx < NN) {
        g_m[idx] = __int_as_float(0xff800000);
        g_denom[idx] = 0.0f;
    }
}

// ============================================================
// K1a: edge-model MLP (persistent, tf32 mma.sync, LDS.128 operands)
// ============================================================
__global__ __launch_bounds__(256, 1) void edgeE_kernel(
    const float* __restrict__ nf, const float* __restrict__ ef,
    const int* __restrict__ src, const int* __restrict__ dst,
    const float* __restrict__ We1, const float* __restrict__ be1,
    const float* __restrict__ We2, const float* __restrict__ be2,
    float* __restrict__ uh_e)
{
    extern __shared__ char smem[];
    float* sx   = (float*)(smem + SM_X);
    float* sB1  = (float*)(smem + SM_B1);
    float* sB2  = (float*)(smem + SM_B2);
    float* sbe1 = (float*)(smem + SM_BE1);
    float* sbe2 = (float*)(smem + SM_BE2);

    const int tid = threadIdx.x;
    const int w = tid >> 5, lane = tid & 31;
    const int wm = w & 3, wn = w >> 2;
    const int tig = lane & 3, gid = lane >> 2;

    pack_Bv(sB1, We1, EMIN, HID, tid, 256);
    pack_Bv(sB2, We2, HID, EOUT, tid, 256);
    if (tid < 128) sbe1[tid] = be1[tid];
    if (tid < 64)  sbe2[tid] = be2[tid];
    __syncthreads();

    for (int tile = blockIdx.x; tile < NTILES; tile += gridDim.x) {
        __syncthreads();
        gather_tile(sx, nf, ef, src, dst, tile, tid);
        __syncthreads();

        // ---- layer 1: [128e x 160k] x [160k x 128n] ----
        float acc[2][8][4];
        #pragma unroll
        for (int mi = 0; mi < 2; mi++)
            #pragma unroll
            for (int ni = 0; ni < 8; ni++)
                #pragma unroll
                for (int c = 0; c < 4; c++) acc[mi][ni][c] = 0.0f;

        #pragma unroll 4
        for (int kt = 0; kt < KT1; kt++) {
            uint32_t a[2][4];
            #pragma unroll
            for (int mi = 0; mi < 2; mi++) {
                const float4 t = *(const float4*)&sx[((2 * wm + mi) * KT1 + kt) * FB + lane * 4];
                a[mi][0] = __float_as_uint(t.x); a[mi][1] = __float_as_uint(t.y);
                a[mi][2] = __float_as_uint(t.z); a[mi][3] = __float_as_uint(t.w);
            }
            #pragma unroll
            for (int np = 0; np < 4; np++) {
                const float4 t = *(const float4*)&sB1[((kt * 8 + wn * 4 + np) * 32 + lane) * 4];
                const uint32_t b00 = __float_as_uint(t.x), b01 = __float_as_uint(t.y);
                const uint32_t b10 = __float_as_uint(t.z), b11 = __float_as_uint(t.w);
                #pragma unroll
                for (int mi = 0; mi < 2; mi++) {
                    mma8(acc[mi][2 * np],     a[mi], b00, b01);
                    mma8(acc[mi][2 * np + 1], a[mi], b10, b11);
                }
            }
        }
        __syncthreads();

        // ---- relu+bias -> h fragment blocks (alias over sx) ----
        float* sh = sx;
        #pragma unroll
        for (int mi = 0; mi < 2; mi++) {
            const int mt = 2 * wm + mi;
            #pragma unroll
            for (int ni = 0; ni < 8; ni++) {
                const int j0 = wn * 64 + ni * 8 + 2 * tig;
                const int jt = j0 >> 3;
                const float b0 = sbe1[j0], b1 = sbe1[j0 + 1];
                float* base = sh + (mt * JT2 + jt) * FB + gid * 16 + (j0 & 3) * 4 + 2 * ((j0 >> 2) & 1);
                base[0] = tfbits(fmaxf(acc[mi][ni][0] + b0, 0.f));
                base[4] = tfbits(fmaxf(acc[mi][ni][1] + b1, 0.f));
                base[1] = tfbits(fmaxf(acc[mi][ni][2] + b0, 0.f));
                base[5] = tfbits(fmaxf(acc[mi][ni][3] + b1, 0.f));
            }
        }
        __syncthreads();

        // ---- layer 2: [128e x 128k] x [128k x 64n] ----
        float acc2[2][4][4];
        #pragma unroll
        for (int mi = 0; mi < 2; mi++)
            #pragma unroll
            for (int ni = 0; ni < 4; ni++)
                #pragma unroll
                for (int c = 0; c < 4; c++) acc2[mi][ni][c] = 0.0f;

        #pragma unroll 4
        for (int jt = 0; jt < JT2; jt++) {
            uint32_t a[2][4];
            #pragma unroll
            for (int mi = 0; mi < 2; mi++) {
                const float4 t = *(const float4*)&sh[((2 * wm + mi) * JT2 + jt) * FB + lane * 4];
                a[mi][0] = __float_as_uint(t.x); a[mi][1] = __float_as_uint(t.y);
                a[mi][2] = __float_as_uint(t.z); a[mi][3] = __float_as_uint(t.w);
            }
            #pragma unroll
            for (int np = 0; np < 2; np++) {
                const float4 t = *(const float4*)&sB2[((jt * 4 + wn * 2 + np) * 32 + lane) * 4];
                const uint32_t b00 = __float_as_uint(t.x), b01 = __float_as_uint(t.y);
                const uint32_t b10 = __float_as_uint(t.z), b11 = __float_as_uint(t.w);
                #pragma unroll
                for (int mi = 0; mi < 2; mi++) {
                    mma8(acc2[mi][2 * np],     a[mi], b00, b01);
                    mma8(acc2[mi][2 * np + 1], a[mi], b10, b11);
                }
            }
        }

        // ---- epilogue: bias + store uh_e ----
        #pragma unroll
        for (int mi = 0; mi < 2; mi++) {
            const int e0 = tile * TILE + wm * 32 + mi * 16 + gid;
            #pragma unroll
            for (int ni = 0; ni < 4; ni++) {
                const int o = wn * 32 + ni * 8 + 2 * tig;
                const float b0 = sbe2[o], b1 = sbe2[o + 1];
                float2 v0, v1;
                v0.x = acc2[mi][ni][0] + b0; v0.y = acc2[mi][ni][1] + b1;
                v1.x = acc2[mi][ni][2] + b0; v1.y = acc2[mi][ni][3] + b1;
                *(float2*)&uh_e[(size_t)e0 * EOUT + o] = v0;
                *(float2*)&uh_e[(size_t)(e0 + 8) * EOUT + o] = v1;
            }
        }
    }
}

// ============================================================
// K1b: attention MLP + logits (persistent, tf32 mma.sync)
// ============================================================
__global__ __launch_bounds__(256, 1) void edgeA_kernel(
    const float* __restrict__ nf, const float* __restrict__ ef,
    const int* __restrict__ src, const int* __restrict__ dst,
    const float* __restrict__ Wa1, const float* __restrict__ ba1,
    const float* __restrict__ Wa2, const float* __restrict__ ba2)
{
    extern __shared__ char smem[];
    float* sx    = (float*)(smem + SM_X);
    float* sB1   = (float*)(smem + SM_B1);
    float* sba1  = (float*)(smem + SM_BA1);
    float* swa2  = (float*)(smem + SM_WA2);
    float* spart = (float*)(smem + SM_PART);

    const int tid = threadIdx.x;
    const int w = tid >> 5, lane = tid & 31;
    const int wm = w & 3, wn = w >> 2;
    const int tig = lane & 3, gid = lane >> 2;

    pack_Bv(sB1, Wa1, EMIN, HID, tid, 256);
    if (tid < 128) { sba1[tid] = ba1[tid]; swa2[tid] = Wa2[tid]; }
    const float ba2v = ba2[0];
    __syncthreads();

    for (int tile = blockIdx.x; tile < NTILES; tile += gridDim.x) {
        __syncthreads();
        gather_tile(sx, nf, ef, src, dst, tile, tid);
        __syncthreads();

        float acc[2][8][4];
        #pragma unroll
        for (int mi = 0; mi < 2; mi++)
            #pragma unroll
            for (int ni = 0; ni < 8; ni++)
                #pragma unroll
                for (int c = 0; c < 4; c++) acc[mi][ni][c] = 0.0f;

        #pragma unroll 4
        for (int kt = 0; kt < KT1; kt++) {
            uint32_t a[2][4];
            #pragma unroll
            for (int mi = 0; mi < 2; mi++) {
                const float4 t = *(const float4*)&sx[((2 * wm + mi) * KT1 + kt) * FB + lane * 4];
                a[mi][0] = __float_as_uint(t.x); a[mi][1] = __float_as_uint(t.y);
                a[mi][2] = __float_as_uint(t.z); a[mi][3] = __float_as_uint(t.w);
            }
            #pragma unroll
            for (int np = 0; np < 4; np++) {
                const float4 t = *(const float4*)&sB1[((kt * 8 + wn * 4 + np) * 32 + lane) * 4];
                const uint32_t b00 = __float_as_uint(t.x), b01 = __float_as_uint(t.y);
                const uint32_t b10 = __float_as_uint(t.z), b11 = __float_as_uint(t.w);
                #pragma unroll
                for (int mi = 0; mi < 2; mi++) {
                    mma8(acc[mi][2 * np],     a[mi], b00, b01);
                    mma8(acc[mi][2 * np + 1], a[mi], b10, b11);
                }
            }
        }

        // ---- logit = sum_j relu(h+b)*wa2[j], in-register reduction ----
        float part[2][2] = {{0.f, 0.f}, {0.f, 0.f}};
        #pragma unroll
        for (int ni = 0; ni < 8; ni++) {
            const int j0 = wn * 64 + ni * 8 + 2 * tig;
            const float w0 = swa2[j0], w1 = swa2[j0 + 1];
            const float b0 = sba1[j0], b1 = sba1[j0 + 1];
            #pragma unroll
            for (int mi = 0; mi < 2; mi++) {
                part[mi][0] += fmaxf(acc[mi][ni][0] + b0, 0.f) * w0
                             + fmaxf(acc[mi][ni][1] + b1, 0.f) * w1;
                part[mi][1] += fmaxf(acc[mi][ni][2] + b0, 0.f) * w0
                             + fmaxf(acc[mi][ni][3] + b1, 0.f) * w1;
            }
        }
        #pragma unroll
        for (int mi = 0; mi < 2; mi++)
            #pragma unroll
            for (int h2 = 0; h2 < 2; h2++) {
                float v = part[mi][h2];
                v += __shfl_xor_sync(0xffffffff, v, 1);
                v += __shfl_xor_sync(0xffffffff, v, 2);
                if (tig == 0)
                    spart[wn * 128 + wm * 32 + mi * 16 + h2 * 8 + gid] = v;
            }
        __syncthreads();
        if (tid < 128) {
            const int e = tile * TILE + tid;
            const float logit = spart[tid] + spart[128 + tid] + ba2v;
            g_logits[e] = logit;
            atomicMaxFloat(&g_m[dst[e]], logit);
        }
    }
}

// ============================================================
// K2: ex = exp(logit - m[dst]); denom[dst] += ex
// ============================================================
__global__ void softmax_kernel(const int* __restrict__ dst) {
    int e = blockIdx.x * blockDim.x + threadIdx.x;
    int d = dst[e];
    float ex = expf(g_logits[e] - g_m[d]);
    g_ex[e] = ex;
    atomicAdd(&g_denom[d], ex);
}

// ============================================================
// K3: agg[dst] += uh_e * attn (vector red.v4)
// ============================================================
__global__ void agg_kernel(const int* __restrict__ dst,
                           const float* __restrict__ uh_e) {
    size_t idx = (size_t)blockIdx.x * blockDim.x + threadIdx.x;
    int e  = (int)(idx >> 4);
    int jq = (int)(idx & 15);
    int d  = dst[e];
    float w = g_ex[e] / fmaxf(g_denom[d], 1e-38f);
    float4 v = __ldg((const float4*)uh_e + (size_t)e * 16 + jq);
    v.x *= w; v.y *= w; v.z *= w; v.w *= w;
    float* p = &g_agg[(size_t)d * EOUT + jq * 4];
    asm volatile("red.global.add.v4.f32 [%0], {%1, %2, %3, %4};"
                 :: "l"(p), "f"(v.x), "f"(v.y), "f"(v.z), "f"(v.w) : "memory");
}

// ============================================================
// K4: node MLP (scalar f32x2 path, known good)
// ============================================================
__global__ __launch_bounds__(128) void node_kernel(
    const float* __restrict__ nf,
    const float* __restrict__ Wn1, const float* __restrict__ bn1,
    const float* __restrict__ Wn2, const float* __restrict__ bn2,
    float* __restrict__ uh_n)
{
    __shared__ float s_x[NMIN * PITCH];

    const int tid = threadIdx.x;
    const int n0  = blockIdx.x * TE;

    {
        const int e  = tid & 31;
        const int kq = tid >> 5;
        const int n  = n0 + e;
        const bool ok = (n < NN);
        const float4* ag4 = (const float4*)g_agg;
        const float4* nf4 = (const float4*)nf;
        #pragma unroll
        for (int kk = kq; kk < 32; kk += 4) {
            float4 v = make_float4(0.f, 0.f, 0.f, 0.f);
            if (ok) {
                if (kk < 16) v = ag4[(size_t)n * 16 + kk];
                else         v = nf4[(size_t)n * 16 + (kk - 16)];
            }
            const int k = kk * 4;
            s_x[(k + 0) * PITCH + e] = v.x;
            s_x[(k + 1) * PITCH + e] = v.y;
            s_x[(k + 2) * PITCH + e] = v.z;
            s_x[(k + 3) * PITCH + e] = v.w;
        }
    }
    __syncthreads();

    F2 h[16];
    {
        float b = bn1[tid];
        #pragma unroll
        for (int i = 0; i < 16; i++) h[i].f = make_float2(b, b);
    }
    #pragma unroll 2
    for (int k = 0; k < NMIN; k++) {
        const float w1 = __ldg(&Wn1[k * HID + tid]);
        F2 w; w.f = make_float2(w1, w1);
        const float* row = &s_x[k * PITCH];
        #pragma unroll
        for (int i = 0; i < 16; i++) {
            F2 x; x.f = *(const float2*)&row[2 * i];
            fma2(h[i], x, w);
        }
    }
    __syncthreads();
    float* s_h = s_x;
    #pragma unroll
    for (int i = 0; i < 16; i++) {
        float2 v = h[i].f;
        v.x = fmaxf(v.x, 0.0f); v.y = fmaxf(v.y, 0.0f);
        *(float2*)&s_h[tid * PITCH + 2 * i] = v;
    }
    __syncthreads();

    {
        const int o     = tid & 63;
        const int half  = tid >> 6;
        const int ebase = half * 16;
        F2 acc[8];
        const float b2 = bn2[o];
        #pragma unroll
        for (int i = 0; i < 8; i++) acc[i].f = make_float2(b2, b2);

        #pragma unroll 2
        for (int j = 0; j < HID; j++) {
            const float w = __ldg(&Wn2[j * DOUT + o]);
            F2 w2; w2.f = make_float2(w, w);
            const float* row = &s_h[j * PITCH + ebase];
            #pragma unroll
            for (int i = 0; i < 8; i++) {
                F2 x; x.f = *(const float2*)&row[2 * i];
                fma2(acc[i], x, w2);
            }
        }
        #pragma unroll
        for (int i = 0; i < 8; i++) {
            int na = n0 + ebase + 2 * i;
            int nb = na + 1;
            if (na < NN) uh_n[(size_t)na * DOUT + o] = acc[i].f.x;
            if (nb < NN) uh_n[(size_t)nb * DOUT + o] = acc[i].f.y;
        }
    }
}

// ============================================================
extern "C" void kernel_launch(void* const* d_in, const int* in_sizes, int n_in,
                              void* d_out, int out_size) {
    const float* nf  = (const float*)d_in[0];
    const float* ef  = (const float*)d_in[1];
    const int*   src = (const int*)d_in[2];
    const int*   dst = (const int*)d_in[3];
    const float* We1 = (const float*)d_in[4];
    const float* be1 = (const float*)d_in[5];
    const float* We2 = (const float*)d_in[6];
    const float* be2 = (const float*)d_in[7];
    const float* Wa1 = (const float*)d_in[8];
    const float* ba1 = (const float*)d_in[9];
    const float* Wa2 = (const float*)d_in[10];
    const float* ba2 = (const float*)d_in[11];
    const float* Wn1 = (const float*)d_in[12];
    const float* bn1 = (const float*)d_in[13];
    const float* Wn2 = (const float*)d_in[14];
    const float* bn2 = (const float*)d_in[15];

    float* out  = (float*)d_out;
    float* uh_n = out;
    float* uh_e = out + (size_t)NN * DOUT;

    static bool attr_set = false;
    if (!attr_set) {
        cudaFuncSetAttribute(edgeE_kernel, cudaFuncAttributeMaxDynamicSharedMemorySize, SMEM_E);
        cudaFuncSetAttribute(edgeA_kernel, cudaFuncAttributeMaxDynamicSharedMemorySize, SMEM_A);
        attr_set = true;
    }

    init_kernel<<<(NN * 64) / 256, 256>>>();
    edgeE_kernel<<<GRID_P, 256, SMEM_E>>>(nf, ef, src, dst, We1, be1, We2, be2, uh_e);
    edgeA_kernel<<<GRID_P, 256, SMEM_A>>>(nf, ef, src, dst, Wa1, ba1, Wa2, ba2);
    softmax_kernel<<<E_TOTAL / 256, 256>>>(dst);
    agg_kernel<<<(E_TOTAL * 16) / 256, 256>>>(dst, uh_e);
    node_kernel<<<(NN + TE - 1) / TE, 128>>>(nf, Wn1, bn1, Wn2, bn2, uh_n);
}

// round 10
// speedup vs baseline: 1.0615x; 1.0615x over previous
#include <cuda_runtime.h>
#include <cuda_bf16.h>
#include <math.h>
#include <stdint.h>

// ----- problem constants -----
#define E_TOTAL 800000
#define NN      50000
#define DIN     64
#define EIN     32
#define EMIN    160
#define HID     128
#define EOUT    64
#define NMIN    128
#define DOUT    64

#define TILE    64
#define NTILES  (E_TOTAL / TILE)   // 12500
#define GRID_P  148
#define NTHR    512

#define TE      32
#define PITCH   34

// fragment-block: per (mt,kt) 132 floats (528B): lane*4 + reg, +4 pad
#define FB      132
#define KT1     20
#define JT2     16
#define MT      4       // 64 rows / 16

// ----- scratch -----
__device__ float g_logits[E_TOTAL];
__device__ float g_ex[E_TOTAL];
__device__ float g_m[NN];
__device__ float g_denom[NN];
__device__ float g_agg[(size_t)NN * EOUT];
__device__ float g_Wa1f[EMIN * HID];   // Wa1 pre-packed into B-fragment order

// ----- smem layout (bytes) -----
#define SM_X     0
#define SM_H     (MT * KT1 * FB * 4)          // 42240
#define SM_B1    (SM_H + MT * JT2 * FB * 4)   // 42240+33792=76032
#define SM_B2    (SM_B1 + EMIN * HID * 4)     // +81920 = 157952
#define SM_BE1   (SM_B2 + HID * EOUT * 4)     // +32768 = 190720
#define SM_BE2   (SM_BE1 + 512)
#define SM_BA1   (SM_BE2 + 256)
#define SM_WA2   (SM_BA1 + 512)
#define SM_PART  (SM_WA2 + 512)
#define SMEM_F   (SM_PART + 1024)             // 193536

// ============================================================ helpers
union F2 { float2 f; unsigned long long u; };
__device__ __forceinline__ void fma2(F2& acc, F2 x, F2 w) {
    asm("fma.rn.f32x2 %0, %1, %2, %0;" : "+l"(acc.u) : "l"(x.u), "l"(w.u));
}
__device__ __forceinline__ void atomicMaxFloat(float* addr, float v) {
    if (v >= 0.0f) atomicMax((int*)addr, __float_as_int(v));
    else           atomicMin((unsigned int*)addr, __float_as_uint(v));
}
__device__ __forceinline__ uint32_t f2tf(float f) {
    uint32_t r; asm("cvt.rna.tf32.f32 %0, %1;" : "=r"(r) : "f"(f)); return r;
}
__device__ __forceinline__ float tfbits(float f) { return __uint_as_float(f2tf(f)); }

__device__ __forceinline__ void mma8(float* d, const uint32_t* a, uint32_t b0, uint32_t b1) {
    asm volatile(
        "mma.sync.aligned.m16n8k8.row.col.f32.tf32.tf32.f32 "
        "{%0,%1,%2,%3}, {%4,%5,%6,%7}, {%8,%9}, {%0,%1,%2,%3};"
        : "+f"(d[0]), "+f"(d[1]), "+f"(d[2]), "+f"(d[3])
        : "r"(a[0]), "r"(a[1]), "r"(a[2]), "r"(a[3]), "r"(b0), "r"(b1));
}

// pack [K x N] row-major weight into paired B-fragment layout
__device__ __forceinline__ void pack_Bv(float* fb, const float* __restrict__ W,
                                        int K, int N, int tid, int nthr)
{
    const int NPB = N >> 4;
    for (int idx = tid; idx < K * N; idx += nthr) {
        const int k = idx / N, n = idx - k * N;
        const int lane = ((n & 7) << 2) + (k & 3);
        const int blk = (k >> 3) * NPB + (n >> 4);
        fb[(blk * 32 + lane) * 4 + ((n >> 3) & 1) * 2 + ((k >> 2) & 1)] = tfbits(W[idx]);
    }
}

// ============================================================
// K0a: init scratch
// ============================================================
__global__ void init_kernel() {
    int idx = blockIdx.x * blockDim.x + threadIdx.x;
    g_agg[idx] = 0.0f;
    if (idx < NN) {
        g_m[idx] = __int_as_float(0xff800000);
        g_denom[idx] = 0.0f;
    }
}

// K0b: pre-pack Wa1 into global fragment order
__global__ void prep_kernel(const float* __restrict__ Wa1) {
    int idx = blockIdx.x * blockDim.x + threadIdx.x;   // 20480
    int k = idx >> 7, n = idx & 127;
    int lane = ((n & 7) << 2) + (k & 3);
    int blk = (k >> 3) * 8 + (n >> 4);
    g_Wa1f[(blk * 32 + lane) * 4 + ((n >> 3) & 1) * 2 + ((k >> 2) & 1)] = tfbits(Wa1[idx]);
}

// ============================================================
// K1: fused edge kernel (E-MLP + A-MLP + logits), persistent, tf32 mma
// ============================================================
__global__ __launch_bounds__(NTHR, 1) void edge_fused_kernel(
    const float* __restrict__ nf, const float* __restrict__ ef,
    const int* __restrict__ src, const int* __restrict__ dst,
    const float* __restrict__ We1, const float* __restrict__ be1,
    const float* __restrict__ We2, const float* __restrict__ be2,
    const float* __restrict__ ba1, const float* __restrict__ Wa2,
    const float* __restrict__ ba2,
    float* __restrict__ uh_e)
{
    extern __shared__ char smem[];
    float* sx    = (float*)(smem + SM_X);
    float* sh    = (float*)(smem + SM_H);
    float* sB1   = (float*)(smem + SM_B1);
    float* sB2   = (float*)(smem + SM_B2);
    float* sbe1  = (float*)(smem + SM_BE1);
    float* sbe2  = (float*)(smem + SM_BE2);
    float* sba1  = (float*)(smem + SM_BA1);
    float* swa2  = (float*)(smem + SM_WA2);
    float* spart = (float*)(smem + SM_PART);

    const int tid = threadIdx.x;
    const int w = tid >> 5, lane = tid & 31;
    const int wm = w & 3, wn = w >> 2;           // 4 m-tiles x 4 n-groups
    const int tig = lane & 3, gid = lane >> 2;

    pack_Bv(sB1, We1, EMIN, HID, tid, NTHR);
    pack_Bv(sB2, We2, HID, EOUT, tid, NTHR);
    if (tid < 128) { sbe1[tid] = be1[tid]; sba1[tid] = ba1[tid]; swa2[tid] = Wa2[tid]; }
    if (tid < 64)  sbe2[tid] = be2[tid];
    const float ba2v = ba2[0];
    __syncthreads();

    const float4* wa1f = (const float4*)g_Wa1f;

    for (int tile = blockIdx.x; tile < NTILES; tile += gridDim.x) {
        __syncthreads();   // prev tile's sh/spart readers done

        // ---- gather (once per edge): 8 threads/edge, 5 float4 each ----
        {
            const int e_loc = tid >> 3, sub = tid & 7;
            const int e = tile * TILE + e_loc;
            const int s = src[e], d = dst[e];
            const int mt = e_loc >> 4;
            const int rr = e_loc & 15;
            const int g = rr & 7, half = rr >> 3;
            const float4* nfs = (const float4*)nf + (size_t)s * 16;
            const float4* nfd = (const float4*)nf + (size_t)d * 16;
            const float4* efe = (const float4*)ef + (size_t)e * 8;
            #pragma unroll
            for (int i = 0; i < 5; i++) {
                const int f = sub * 5 + i;    // 0..39
                float4 v;
                if (f < 16)      v = nfs[f];
                else if (f < 32) v = nfd[f - 16];
                else             v = efe[f - 32];
                float* base = sx + (mt * KT1 + (f >> 1)) * FB + g * 16 + half + 2 * (f & 1);
                base[0]  = tfbits(v.x);
                base[4]  = tfbits(v.y);
                base[8]  = tfbits(v.z);
                base[12] = tfbits(v.w);
            }
        }
        __syncthreads();

        // ---- layer 1 (E + A fused over one A-fragment stream) ----
        float accE[4][4], accA[4][4];
        #pragma unroll
        for (int ni = 0; ni < 4; ni++)
            #pragma unroll
            for (int c = 0; c < 4; c++) { accE[ni][c] = 0.f; accA[ni][c] = 0.f; }

        float4 bA0 = __ldg(&wa1f[(0 * 8 + wn * 2 + 0) * 32 + lane]);
        float4 bA1 = __ldg(&wa1f[(0 * 8 + wn * 2 + 1) * 32 + lane]);

        #pragma unroll 4
        for (int kt = 0; kt < KT1; kt++) {
            uint32_t a[4];
            {
                const float4 t = *(const float4*)&sx[(wm * KT1 + kt) * FB + lane * 4];
                a[0] = __float_as_uint(t.x); a[1] = __float_as_uint(t.y);
                a[2] = __float_as_uint(t.z); a[3] = __float_as_uint(t.w);
            }
            const int ktn = (kt < KT1 - 1) ? (kt + 1) : kt;   // clamp: no uninit read
            float4 nA0 = __ldg(&wa1f[(ktn * 8 + wn * 2 + 0) * 32 + lane]);
            float4 nA1 = __ldg(&wa1f[(ktn * 8 + wn * 2 + 1) * 32 + lane]);
            {
                const float4 t = *(const float4*)&sB1[((kt * 8 + wn * 2 + 0) * 32 + lane) * 4];
                mma8(accE[0], a, __float_as_uint(t.x), __float_as_uint(t.y));
                mma8(accE[1], a, __float_as_uint(t.z), __float_as_uint(t.w));
            }
            {
                const float4 t = *(const float4*)&sB1[((kt * 8 + wn * 2 + 1) * 32 + lane) * 4];
                mma8(accE[2], a, __float_as_uint(t.x), __float_as_uint(t.y));
                mma8(accE[3], a, __float_as_uint(t.z), __float_as_uint(t.w));
            }
            mma8(accA[0], a, __float_as_uint(bA0.x), __float_as_uint(bA0.y));
            mma8(accA[1], a, __float_as_uint(bA0.z), __float_as_uint(bA0.w));
            mma8(accA[2], a, __float_as_uint(bA1.x), __float_as_uint(bA1.y));
            mma8(accA[3], a, __float_as_uint(bA1.z), __float_as_uint(bA1.w));
            bA0 = nA0; bA1 = nA1;
        }

        // ---- epilogue E: relu+bias -> h fragment blocks ----
        #pragma unroll
        for (int ni = 0; ni < 4; ni++) {
            const int j0 = wn * 32 + ni * 8 + 2 * tig;
            const int jt = wn * 4 + ni;
            const float b0 = sbe1[j0], b1 = sbe1[j0 + 1];
            float* base = sh + (wm * JT2 + jt) * FB + gid * 16 + (j0 & 3) * 4 + 2 * ((j0 >> 2) & 1);
            base[0] = tfbits(fmaxf(accE[ni][0] + b0, 0.f));
            base[4] = tfbits(fmaxf(accE[ni][1] + b1, 0.f));
            base[1] = tfbits(fmaxf(accE[ni][2] + b0, 0.f));
            base[5] = tfbits(fmaxf(accE[ni][3] + b1, 0.f));
        }

        // ---- epilogue A: logit partials ----
        {
            float part[2] = {0.f, 0.f};
            #pragma unroll
            for (int ni = 0; ni < 4; ni++) {
                const int j0 = wn * 32 + ni * 8 + 2 * tig;
                const float w0 = swa2[j0], w1 = swa2[j0 + 1];
                const float b0 = sba1[j0], b1 = sba1[j0 + 1];
                part[0] += fmaxf(accA[ni][0] + b0, 0.f) * w0
                         + fmaxf(accA[ni][1] + b1, 0.f) * w1;
                part[1] += fmaxf(accA[ni][2] + b0, 0.f) * w0
                         + fmaxf(accA[ni][3] + b1, 0.f) * w1;
            }
            #pragma unroll
            for (int h2 = 0; h2 < 2; h2++) {
                float v = part[h2];
                v += __shfl_xor_sync(0xffffffff, v, 1);
                v += __shfl_xor_sync(0xffffffff, v, 2);
                if (tig == 0)
                    spart[wn * 64 + wm * 16 + h2 * 8 + gid] = v;
            }
        }
        __syncthreads();

        // ---- layer 2 (E): [64e x 128k] x [128k x 64n] ----
        float acc2[2][4];
        #pragma unroll
        for (int ni = 0; ni < 2; ni++)
            #pragma unroll
            for (int c = 0; c < 4; c++) acc2[ni][c] = 0.f;

        #pragma unroll 4
        for (int jt = 0; jt < JT2; jt++) {
            uint32_t a[4];
            {
                const float4 t = *(const float4*)&sh[(wm * JT2 + jt) * FB + lane * 4];
                a[0] = __float_as_uint(t.x); a[1] = __float_as_uint(t.y);
                a[2] = __float_as_uint(t.z); a[3] = __float_as_uint(t.w);
            }
            const float4 t = *(const float4*)&sB2[((jt * 4 + wn) * 32 + lane) * 4];
            mma8(acc2[0], a, __float_as_uint(t.x), __float_as_uint(t.y));
            mma8(acc2[1], a, __float_as_uint(t.z), __float_as_uint(t.w));
        }

        // ---- store uh_e + logits ----
        {
            const int e0 = tile * TILE + wm * 16 + gid;
            #pragma unroll
            for (int ni = 0; ni < 2; ni++) {
                const int o = wn * 16 + ni * 8 + 2 * tig;
                const float b0 = sbe2[o], b1 = sbe2[o + 1];
                float2 v0, v1;
                v0.x = acc2[ni][0] + b0; v0.y = acc2[ni][1] + b1;
                v1.x = acc2[ni][2] + b0; v1.y = acc2[ni][3] + b1;
                *(float2*)&uh_e[(size_t)e0 * EOUT + o] = v0;
                *(float2*)&uh_e[(size_t)(e0 + 8) * EOUT + o] = v1;
            }
        }
        if (tid < TILE) {
            const int e = tile * TILE + tid;
            const float logit = spart[tid] + spart[64 + tid]
                              + spart[128 + tid] + spart[192 + tid] + ba2v;
            g_logits[e] = logit;
            atomicMaxFloat(&g_m[dst[e]], logit);
        }
    }
}

// ============================================================
// K2: ex = exp(logit - m[dst]); denom[dst] += ex
// ============================================================
__global__ void softmax_kernel(const int* __restrict__ dst) {
    int e = blockIdx.x * blockDim.x + threadIdx.x;
    int d = dst[e];
    float ex = expf(g_logits[e] - g_m[d]);
    g_ex[e] = ex;
    atomicAdd(&g_denom[d], ex);
}

// ============================================================
// K3: agg[dst] += uh_e * attn (vector red.v4)
// ============================================================
__global__ void agg_kernel(const int* __restrict__ dst,
                           const float* __restrict__ uh_e) {
    size_t idx = (size_t)blockIdx.x * blockDim.x + threadIdx.x;
    int e  = (int)(idx >> 4);
    int jq = (int)(idx & 15);
    int d  = dst[e];
    float w = g_ex[e] / fmaxf(g_denom[d], 1e-38f);
    float4 v = __ldg((const float4*)uh_e + (size_t)e * 16 + jq);
    v.x *= w; v.y *= w; v.z *= w; v.w *= w;
    float* p = &g_agg[(size_t)d * EOUT + jq * 4];
    asm volatile("red.global.add.v4.f32 [%0], {%1, %2, %3, %4};"
                 :: "l"(p), "f"(v.x), "f"(v.y), "f"(v.z), "f"(v.w) : "memory");
}

// ============================================================
// K4: node MLP (scalar f32x2 path, known good)
// ============================================================
__global__ __launch_bounds__(128) void node_kernel(
    const float* __restrict__ nf,
    const float* __restrict__ Wn1, const float* __restrict__ bn1,
    const float* __restrict__ Wn2, const float* __restrict__ bn2,
    float* __restrict__ uh_n)
{
    __shared__ float s_x[NMIN * PITCH];

    const int tid = threadIdx.x;
    const int n0  = blockIdx.x * TE;

    {
        const int e  = tid & 31;
        const int kq = tid >> 5;
        const int n  = n0 + e;
        const bool ok = (n < NN);
        const float4* ag4 = (const float4*)g_agg;
        const float4* nf4 = (const float4*)nf;
        #pragma unroll
        for (int kk = kq; kk < 32; kk += 4) {
            float4 v = make_float4(0.f, 0.f, 0.f, 0.f);
            if (ok) {
                if (kk < 16) v = ag4[(size_t)n * 16 + kk];
                else         v = nf4[(size_t)n * 16 + (kk - 16)];
            }
            const int k = kk * 4;
            s_x[(k + 0) * PITCH + e] = v.x;
            s_x[(k + 1) * PITCH + e] = v.y;
            s_x[(k + 2) * PITCH + e] = v.z;
            s_x[(k + 3) * PITCH + e] = v.w;
        }
    }
    __syncthreads();

    F2 h[16];
    {
        float b = bn1[tid];
        #pragma unroll
        for (int i = 0; i < 16; i++) h[i].f = make_float2(b, b);
    }
    #pragma unroll 2
    for (int k = 0; k < NMIN; k++) {
        const float w1 = __ldg(&Wn1[k * HID + tid]);
        F2 w; w.f = make_float2(w1, w1);
        const float* row = &s_x[k * PITCH];
        #pragma unroll
        for (int i = 0; i < 16; i++) {
            F2 x; x.f = *(const float2*)&row[2 * i];
            fma2(h[i], x, w);
        }
    }
    __syncthreads();
    float* s_h = s_x;
    #pragma unroll
    for (int i = 0; i < 16; i++) {
        float2 v = h[i].f;
        v.x = fmaxf(v.x, 0.0f); v.y = fmaxf(v.y, 0.0f);
        *(float2*)&s_h[tid * PITCH + 2 * i] = v;
    }
    __syncthreads();

    {
        const int o     = tid & 63;
        const int half  = tid >> 6;
        const int ebase = half * 16;
        F2 acc[8];
        const float b2 = bn2[o];
        #pragma unroll
        for (int i = 0; i < 8; i++) acc[i].f = make_float2(b2, b2);

        #pragma unroll 2
        for (int j = 0; j < HID; j++) {
            const float w = __ldg(&Wn2[j * DOUT + o]);
            F2 w2; w2.f = make_float2(w, w);
            const float* row = &s_h[j * PITCH + ebase];
            #pragma unroll
            for (int i = 0; i < 8; i++) {
                F2 x; x.f = *(const float2*)&row[2 * i];
                fma2(acc[i], x, w2);
            }
        }
        #pragma unroll
        for (int i = 0; i < 8; i++) {
            int na = n0 + ebase + 2 * i;
            int nb = na + 1;
            if (na < NN) uh_n[(size_t)na * DOUT + o] = acc[i].f.x;
            if (nb < NN) uh_n[(size_t)nb * DOUT + o] = acc[i].f.y;
        }
    }
}

// ============================================================
extern "C" void kernel_launch(void* const* d_in, const int* in_sizes, int n_in,
                              void* d_out, int out_size) {
    const float* nf  = (const float*)d_in[0];
    const float* ef  = (const float*)d_in[1];
    const int*   src = (const int*)d_in[2];
    const int*   dst = (const int*)d_in[3];
    const float* We1 = (const float*)d_in[4];
    const float* be1 = (const float*)d_in[5];
    const float* We2 = (const float*)d_in[6];
    const float* be2 = (const float*)d_in[7];
    const float* Wa1 = (const float*)d_in[8];
    const float* ba1 = (const float*)d_in[9];
    const float* Wa2 = (const float*)d_in[10];
    const float* ba2 = (const float*)d_in[11];
    const float* Wn1 = (const float*)d_in[12];
    const float* bn1 = (const float*)d_in[13];
    const float* Wn2 = (const float*)d_in[14];
    const float* bn2 = (const float*)d_in[15];

    float* out  = (float*)d_out;
    float* uh_n = out;
    float* uh_e = out + (size_t)NN * DOUT;

    static bool attr_set = false;
    if (!attr_set) {
        cudaFuncSetAttribute(edge_fused_kernel,
                             cudaFuncAttributeMaxDynamicSharedMemorySize, SMEM_F);
        attr_set = true;
    }

    init_kernel<<<(NN * 64) / 256, 256>>>();
    prep_kernel<<<(EMIN * HID) / 256, 256>>>(Wa1);
    edge_fused_kernel<<<GRID_P, NTHR, SMEM_F>>>(nf, ef, src, dst,
                                                We1, be1, We2, be2,
                                                ba1, Wa2, ba2, uh_e);
    softmax_kernel<<<E_TOTAL / 256, 256>>>(dst);
    agg_kernel<<<(E_TOTAL * 16) / 256, 256>>>(dst, uh_e);
    node_kernel<<<(NN + TE - 1) / TE, 128>>>(nf, Wn1, bn1, Wn2, bn2, uh_n);
}

// round 12
// speedup vs baseline: 1.4600x; 1.3754x over previous
#include <cuda_runtime.h>
#include <cuda_fp16.h>
#include <math.h>
#include <stdint.h>

// ----- problem constants -----
#define E_TOTAL 800000
#define NN      50000
#define DIN     64
#define EIN     32
#define EMIN    160
#define HID     128
#define EOUT    64
#define NMIN    128
#define DOUT    64

#define TILE    64
#define NTILES  (E_TOTAL / TILE)   // 12500
#define GRID_P  148
#define NTHR    512

#define TE      32
#define PITCH   34

// fp16 fragment tiling
#define FB      132     // b32 words per (mt,kt) fragment block (528B)
#define KT1H    10      // layer-1 k16-tiles (160/16)
#define JT2H    8       // layer-2 k16-tiles (128/16)
#define MT      4       // 64 rows / 16

// ----- scratch -----
__device__ float g_logits[E_TOTAL];
__device__ float g_ex[E_TOTAL];
__device__ float g_m[NN];
__device__ float g_denom[NN];
__device__ float g_agg[(size_t)NN * EOUT];

// ----- smem layout (bytes) -----
#define SM_X     0
#define SM_H     (MT * KT1H * FB * 4)            // 21120
#define SM_B1E   (SM_H + MT * JT2H * FB * 4)     // 21120+16896=38016
#define SM_B1A   (SM_B1E + KT1H * 16 * 64 * 4)   // +40960 = 78976
#define SM_B2    (SM_B1A + KT1H * 16 * 64 * 4)   // +40960 = 119936
#define SM_BE1   (SM_B2 + JT2H * 8 * 64 * 4)     // +16384 = 136320
#define SM_BE2   (SM_BE1 + 512)
#define SM_BA1   (SM_BE2 + 256)
#define SM_WA2   (SM_BA1 + 512)
#define SM_PART  (SM_WA2 + 512)
#define SMEM_F   (SM_PART + 1024)                // 139136

// ============================================================ helpers
union F2 { float2 f; unsigned long long u; };
__device__ __forceinline__ void fma2(F2& acc, F2 x, F2 w) {
    asm("fma.rn.f32x2 %0, %1, %2, %0;" : "+l"(acc.u) : "l"(x.u), "l"(w.u));
}
__device__ __forceinline__ void atomicMaxFloat(float* addr, float v) {
    if (v >= 0.0f) atomicMax((int*)addr, __float_as_int(v));
    else           atomicMin((unsigned int*)addr, __float_as_uint(v));
}
__device__ __forceinline__ uint32_t pack2h(float lo, float hi) {
    __half2 h = __floats2half2_rn(lo, hi);
    return *(uint32_t*)&h;
}

__device__ __forceinline__ void mma16(float* d, const uint32_t* a, uint32_t b0, uint32_t b1) {
    asm volatile(
        "mma.sync.aligned.m16n8k16.row.col.f32.f16.f16.f32 "
        "{%0,%1,%2,%3}, {%4,%5,%6,%7}, {%8,%9}, {%0,%1,%2,%3};"
        : "+f"(d[0]), "+f"(d[1]), "+f"(d[2]), "+f"(d[3])
        : "r"(a[0]), "r"(a[1]), "r"(a[2]), "r"(a[3]), "r"(b0), "r"(b1));
}

// pack [K x N] row-major fp32 weight into fp16 m16n8k16 B-fragment layout.
// per (kt,n8) block: 32 lanes x 2 b32 (4 halves);
//   lane = (n&7)*4 + ((k&7)>>1), reg = (k>>3)&1, pos = k&1
__device__ __forceinline__ void pack_Bh(__half* fb, const float* __restrict__ W,
                                        int K, int N, int tid, int nthr)
{
    const int NPB = N >> 3;
    for (int idx = tid; idx < K * N; idx += nthr) {
        const int k = idx / N, n = idx - k * N;
        const int lane = ((n & 7) << 2) + ((k & 7) >> 1);
        const int blk  = (k >> 4) * NPB + (n >> 3);
        const int reg  = (k >> 3) & 1;
        const int pos  = k & 1;
        const int half_idx = (blk * 32 + lane) * 4 + reg * 2 + pos;
        fb[half_idx] = __float2half_rn(W[idx]);
    }
}

// ============================================================
// K0: init scratch
// ============================================================
__global__ void init_kernel() {
    int idx = blockIdx.x * blockDim.x + threadIdx.x;
    g_agg[idx] = 0.0f;
    if (idx < NN) {
        g_m[idx] = __int_as_float(0xff800000);
        g_denom[idx] = 0.0f;
    }
}

// ============================================================
// K1: fused edge kernel (E-MLP + A-MLP + logits), persistent, fp16 mma
// ============================================================
__global__ __launch_bounds__(NTHR, 1) void edge_fused_kernel(
    const float* __restrict__ nf, const float* __restrict__ ef,
    const int* __restrict__ src, const int* __restrict__ dst,
    const float* __restrict__ We1, const float* __restrict__ be1,
    const float* __restrict__ We2, const float* __restrict__ be2,
    const float* __restrict__ Wa1, const float* __restrict__ ba1,
    const float* __restrict__ Wa2, const float* __restrict__ ba2,
    float* __restrict__ uh_e)
{
    extern __shared__ char smem[];
    uint32_t* sxu  = (uint32_t*)(smem + SM_X);
    uint32_t* shu  = (uint32_t*)(smem + SM_H);
    uint32_t* sB1E = (uint32_t*)(smem + SM_B1E);
    uint32_t* sB1A = (uint32_t*)(smem + SM_B1A);
    uint32_t* sB2  = (uint32_t*)(smem + SM_B2);
    float* sbe1  = (float*)(smem + SM_BE1);
    float* sbe2  = (float*)(smem + SM_BE2);
    float* sba1  = (float*)(smem + SM_BA1);
    float* swa2  = (float*)(smem + SM_WA2);
    float* spart = (float*)(smem + SM_PART);

    const int tid = threadIdx.x;
    const int w = tid >> 5, lane = tid & 31;
    const int wm = w & 3, wn = w >> 2;           // 4 m-tiles x 4 n-groups(32 cols)
    const int tig = lane & 3, gid = lane >> 2;

    pack_Bh((__half*)sB1E, We1, EMIN, HID, tid, NTHR);
    pack_Bh((__half*)sB1A, Wa1, EMIN, HID, tid, NTHR);
    pack_Bh((__half*)sB2,  We2, HID, EOUT, tid, NTHR);
    if (tid < 128) { sbe1[tid] = be1[tid]; sba1[tid] = ba1[tid]; swa2[tid] = Wa2[tid]; }
    if (tid < 64)  sbe2[tid] = be2[tid];
    const float ba2v = ba2[0];
    __syncthreads();

    for (int tile = blockIdx.x; tile < NTILES; tile += gridDim.x) {
        __syncthreads();   // prev tile's readers done

        // ---- gather (once per edge): 8 threads/edge, 5 float4 each ----
        {
            const int e_loc = tid >> 3;
            const int sub   = tid & 7;
            const int e = tile * TILE + e_loc;
            const int s = src[e], d = dst[e];
            const int mt = e_loc >> 4;
            const int rr = e_loc & 15;
            const int g = rr & 7, half = rr >> 3;
            const float4* nfs = (const float4*)nf + (size_t)s * 16;
            const float4* nfd = (const float4*)nf + (size_t)d * 16;
            const float4* efe = (const float4*)ef + (size_t)e * 8;
            #pragma unroll
            for (int i = 0; i < 5; i++) {
                const int f = sub * 5 + i;    // 0..39, covers k = 4f..4f+3
                float4 v;
                if (f < 16)      v = nfs[f];
                else if (f < 32) v = nfd[f - 16];
                else             v = efe[f - 32];
                const int kt    = f >> 2;
                const int tg    = (f & 1) * 2;        // tig of first k-pair
                const int thalf = (f >> 1) & 1;
                const int base  = (mt * KT1H + kt) * FB + (g * 4 + tg) * 4 + half + 2 * thalf;
                sxu[base]     = pack2h(v.x, v.y);
                sxu[base + 4] = pack2h(v.z, v.w);     // next lane (tg+1)
            }
        }
        __syncthreads();

        // ---- layer 1 (E + A fused), k16 steps ----
        float accE[4][4], accA[4][4];
        #pragma unroll
        for (int ni = 0; ni < 4; ni++)
            #pragma unroll
            for (int c = 0; c < 4; c++) { accE[ni][c] = 0.f; accA[ni][c] = 0.f; }

        #pragma unroll
        for (int kt = 0; kt < KT1H; kt++) {
            uint32_t a[4];
            {
                const uint4 t = *(const uint4*)&sxu[(wm * KT1H + kt) * FB + lane * 4];
                a[0] = t.x; a[1] = t.y; a[2] = t.z; a[3] = t.w;
            }
            #pragma unroll
            for (int ni = 0; ni < 4; ni++) {
                const int n8 = wn * 4 + ni;
                const uint2 bE = *(const uint2*)&sB1E[((kt * 16 + n8) * 32 + lane) * 2];
                mma16(accE[ni], a, bE.x, bE.y);
                const uint2 bA = *(const uint2*)&sB1A[((kt * 16 + n8) * 32 + lane) * 2];
                mma16(accA[ni], a, bA.x, bA.y);
            }
        }

        // ---- epilogue E: relu+bias -> h fragment blocks (fp16) ----
        #pragma unroll
        for (int ni = 0; ni < 4; ni++) {
            const int j0 = wn * 32 + ni * 8 + 2 * tig;
            const int jt = wn * 2 + (ni >> 1);
            const int thalf = ni & 1;
            const float b0 = sbe1[j0], b1 = sbe1[j0 + 1];
            const int base = (wm * JT2H + jt) * FB + (gid * 4 + tig) * 4 + 2 * thalf;
            shu[base]     = pack2h(fmaxf(accE[ni][0] + b0, 0.f), fmaxf(accE[ni][1] + b1, 0.f));
            shu[base + 1] = pack2h(fmaxf(accE[ni][2] + b0, 0.f), fmaxf(accE[ni][3] + b1, 0.f));
        }

        // ---- epilogue A: logit partials ----
        {
            float part[2] = {0.f, 0.f};
            #pragma unroll
            for (int ni = 0; ni < 4; ni++) {
                const int j0 = wn * 32 + ni * 8 + 2 * tig;
                const float w0 = swa2[j0], w1 = swa2[j0 + 1];
                const float b0 = sba1[j0], b1 = sba1[j0 + 1];
                part[0] += fmaxf(accA[ni][0] + b0, 0.f) * w0
                         + fmaxf(accA[ni][1] + b1, 0.f) * w1;
                part[1] += fmaxf(accA[ni][2] + b0, 0.f) * w0
                         + fmaxf(accA[ni][3] + b1, 0.f) * w1;
            }
            #pragma unroll
            for (int h2 = 0; h2 < 2; h2++) {
                float v = part[h2];
                v += __shfl_xor_sync(0xffffffff, v, 1);
                v += __shfl_xor_sync(0xffffffff, v, 2);
                if (tig == 0)
                    spart[wn * 64 + wm * 16 + h2 * 8 + gid] = v;
            }
        }
        __syncthreads();

        // ---- layer 2 (E): [64e x 128k] x [128k x 64n], k16 ----
        float acc2[2][4];
        #pragma unroll
        for (int ni = 0; ni < 2; ni++)
            #pragma unroll
            for (int c = 0; c < 4; c++) acc2[ni][c] = 0.f;

        #pragma unroll
        for (int jt = 0; jt < JT2H; jt++) {
            uint32_t a[4];
            {
                const uint4 t = *(const uint4*)&shu[(wm * JT2H + jt) * FB + lane * 4];
                a[0] = t.x; a[1] = t.y; a[2] = t.z; a[3] = t.w;
            }
            #pragma unroll
            for (int ni = 0; ni < 2; ni++) {
                const int n8 = wn * 2 + ni;
                const uint2 b = *(const uint2*)&sB2[((jt * 8 + n8) * 32 + lane) * 2];
                mma16(acc2[ni], a, b.x, b.y);
            }
        }

        // ---- store uh_e + logits ----
        {
            const int e0 = tile * TILE + wm * 16 + gid;
            #pragma unroll
            for (int ni = 0; ni < 2; ni++) {
                const int o = wn * 16 + ni * 8 + 2 * tig;
                const float b0 = sbe2[o], b1 = sbe2[o + 1];
                float2 v0, v1;
                v0.x = acc2[ni][0] + b0; v0.y = acc2[ni][1] + b1;
                v1.x = acc2[ni][2] + b0; v1.y = acc2[ni][3] + b1;
                *(float2*)&uh_e[(size_t)e0 * EOUT + o] = v0;
                *(float2*)&uh_e[(size_t)(e0 + 8) * EOUT + o] = v1;
            }
        }
        if (tid < TILE) {
            const int e = tile * TILE + tid;
            const float logit = spart[tid] + spart[64 + tid]
                              + spart[128 + tid] + spart[192 + tid] + ba2v;
            g_logits[e] = logit;
            atomicMaxFloat(&g_m[dst[e]], logit);
        }
    }
}

// ============================================================
// K2: ex = exp(logit - m[dst]); denom[dst] += ex
// ============================================================
__global__ void softmax_kernel(const int* __restrict__ dst) {
    int e = blockIdx.x * blockDim.x + threadIdx.x;
    int d = dst[e];
    float ex = expf(g_logits[e] - g_m[d]);
    g_ex[e] = ex;
    atomicAdd(&g_denom[d], ex);
}

// ============================================================
// K3: agg[dst] += uh_e * attn (vector red.v4)
// ============================================================
__global__ void agg_kernel(const int* __restrict__ dst,
                           const float* __restrict__ uh_e) {
    size_t idx = (size_t)blockIdx.x * blockDim.x + threadIdx.x;
    int e  = (int)(idx >> 4);
    int jq = (int)(idx & 15);
    int d  = dst[e];
    float w = g_ex[e] / fmaxf(g_denom[d], 1e-38f);
    float4 v = __ldg((const float4*)uh_e + (size_t)e * 16 + jq);
    v.x *= w; v.y *= w; v.z *= w; v.w *= w;
    float* p = &g_agg[(size_t)d * EOUT + jq * 4];
    asm volatile("red.global.add.v4.f32 [%0], {%1, %2, %3, %4};"
                 :: "l"(p), "f"(v.x), "f"(v.y), "f"(v.z), "f"(v.w) : "memory");
}

// ============================================================
// K4: node MLP (scalar f32x2 path, known good)
// ============================================================
__global__ __launch_bounds__(128) void node_kernel(
    const float* __restrict__ nf,
    const float* __restrict__ Wn1, const float* __restrict__ bn1,
    const float* __restrict__ Wn2, const float* __restrict__ bn2,
    float* __restrict__ uh_n)
{
    __shared__ float s_x[NMIN * PITCH];

    const int tid = threadIdx.x;
    const int n0  = blockIdx.x * TE;

    {
        const int e  = tid & 31;
        const int kq = tid >> 5;
        const int n  = n0 + e;
        const bool ok = (n < NN);
        const float4* ag4 = (const float4*)g_agg;
        const float4* nf4 = (const float4*)nf;
        #pragma unroll
        for (int kk = kq; kk < 32; kk += 4) {
            float4 v = make_float4(0.f, 0.f, 0.f, 0.f);
            if (ok) {
                if (kk < 16) v = ag4[(size_t)n * 16 + kk];
                else         v = nf4[(size_t)n * 16 + (kk - 16)];
            }
            const int k = kk * 4;
            s_x[(k + 0) * PITCH + e] = v.x;
            s_x[(k + 1) * PITCH + e] = v.y;
            s_x[(k + 2) * PITCH + e] = v.z;
            s_x[(k + 3) * PITCH + e] = v.w;
        }
    }
    __syncthreads();

    F2 h[16];
    {
        float b = bn1[tid];
        #pragma unroll
        for (int i = 0; i < 16; i++) h[i].f = make_float2(b, b);
    }
    #pragma unroll 2
    for (int k = 0; k < NMIN; k++) {
        const float w1 = __ldg(&Wn1[k * HID + tid]);
        F2 w; w.f = make_float2(w1, w1);
        const float* row = &s_x[k * PITCH];
        #pragma unroll
        for (int i = 0; i < 16; i++) {
            F2 x; x.f = *(const float2*)&row[2 * i];
            fma2(h[i], x, w);
        }
    }
    __syncthreads();
    float* s_h = s_x;
    #pragma unroll
    for (int i = 0; i < 16; i++) {
        float2 v = h[i].f;
        v.x = fmaxf(v.x, 0.0f); v.y = fmaxf(v.y, 0.0f);
        *(float2*)&s_h[tid * PITCH + 2 * i] = v;
    }
    __syncthreads();

    {
        const int o     = tid & 63;
        const int half  = tid >> 6;
        const int ebase = half * 16;
        F2 acc[8];
        const float b2 = bn2[o];
        #pragma unroll
        for (int i = 0; i < 8; i++) acc[i].f = make_float2(b2, b2);

        #pragma unroll 2
        for (int j = 0; j < HID; j++) {
            const float w = __ldg(&Wn2[j * DOUT + o]);
            F2 w2; w2.f = make_float2(w, w);
            const float* row = &s_h[j * PITCH + ebase];
            #pragma unroll
            for (int i = 0; i < 8; i++) {
                F2 x; x.f = *(const float2*)&row[2 * i];
                fma2(acc[i], x, w2);
            }
        }
        #pragma unroll
        for (int i = 0; i < 8; i++) {
            int na = n0 + ebase + 2 * i;
            int nb = na + 1;
            if (na < NN) uh_n[(size_t)na * DOUT + o] = acc[i].f.x;
            if (nb < NN) uh_n[(size_t)nb * DOUT + o] = acc[i].f.y;
        }
    }
}

// ============================================================
extern "C" void kernel_launch(void* const* d_in, const int* in_sizes, int n_in,
                              void* d_out, int out_size) {
    const float* nf  = (const float*)d_in[0];
    const float* ef  = (const float*)d_in[1];
    const int*   src = (const int*)d_in[2];
    const int*   dst = (const int*)d_in[3];
    const float* We1 = (const float*)d_in[4];
    const float* be1 = (const float*)d_in[5];
    const float* We2 = (const float*)d_in[6];
    const float* be2 = (const float*)d_in[7];
    const float* Wa1 = (const float*)d_in[8];
    const float* ba1 = (const float*)d_in[9];
    const float* Wa2 = (const float*)d_in[10];
    const float* ba2 = (const float*)d_in[11];
    const float* Wn1 = (const float*)d_in[12];
    const float* bn1 = (const float*)d_in[13];
    const float* Wn2 = (const float*)d_in[14];
    const float* bn2 = (const float*)d_in[15];

    float* out  = (float*)d_out;
    float* uh_n = out;
    float* uh_e = out + (size_t)NN * DOUT;

    static bool attr_set = false;
    if (!attr_set) {
        cudaFuncSetAttribute(edge_fused_kernel,
                             cudaFuncAttributeMaxDynamicSharedMemorySize, SMEM_F);
        attr_set = true;
    }

    init_kernel<<<(NN * 64) / 256, 256>>>();
    edge_fused_kernel<<<GRID_P, NTHR, SMEM_F>>>(nf, ef, src, dst,
                                                We1, be1, We2, be2,
                                                Wa1, ba1, Wa2, ba2, uh_e);
    softmax_kernel<<<E_TOTAL / 256, 256>>>(dst);
    agg_kernel<<<(E_TOTAL * 16) / 256, 256>>>(dst, uh_e);
    node_kernel<<<(NN + TE - 1) / TE, 128>>>(nf, Wn1, bn1, Wn2, bn2, uh_n);
}

// round 13
// speedup vs baseline: 1.5702x; 1.0755x over previous
#include <cuda_runtime.h>
#include <cuda_fp16.h>
#include <math.h>
#include <stdint.h>

// ----- problem constants -----
#define E_TOTAL 800000
#define NN      50000
#define DIN     64
#define EIN     32
#define EMIN    160
#define HID     128
#define EOUT    64
#define NMIN    128
#define DOUT    64

#define TILE    64
#define NTILES  (E_TOTAL / TILE)   // 12500
#define GRID_P  148
#define NTHR    512

#define TE      32
#define PITCH   34

// fp16 fragment tiling
#define FB      132     // b32 words per (mt,kt) fragment block (528B)
#define KT1H    10      // layer-1 k16-tiles (160/16)
#define JT2H    8       // layer-2 k16-tiles (128/16)
#define MT      4       // 64 rows / 16

// ----- scratch -----
__device__ float g_logits[E_TOTAL];
__device__ float g_ex[E_TOTAL];
__device__ float g_m[NN];
__device__ float g_denom[NN];
__device__ float g_agg[(size_t)NN * EOUT];

// ----- smem layout (bytes) -----
#define XBYTES   (MT * KT1H * FB * 4)            // 21120
#define SM_X0    0
#define SM_X1    XBYTES                          // 21120
#define SM_H     (2 * XBYTES)                    // 42240
#define SM_B1E   (SM_H + MT * JT2H * FB * 4)     // 42240+16896=59136
#define SM_B1A   (SM_B1E + KT1H * 16 * 64 * 4)   // +40960 = 100096
#define SM_B2    (SM_B1A + KT1H * 16 * 64 * 4)   // +40960 = 141056
#define SM_BE1   (SM_B2 + JT2H * 8 * 64 * 4)     // +16384 = 157440
#define SM_BE2   (SM_BE1 + 512)
#define SM_BA1   (SM_BE2 + 256)
#define SM_WA2   (SM_BA1 + 512)
#define SM_PART  (SM_WA2 + 512)
#define SMEM_F   (SM_PART + 1024)                // 160256

// ============================================================ helpers
union F2 { float2 f; unsigned long long u; };
__device__ __forceinline__ void fma2(F2& acc, F2 x, F2 w) {
    asm("fma.rn.f32x2 %0, %1, %2, %0;" : "+l"(acc.u) : "l"(x.u), "l"(w.u));
}
__device__ __forceinline__ void atomicMaxFloat(float* addr, float v) {
    if (v >= 0.0f) atomicMax((int*)addr, __float_as_int(v));
    else           atomicMin((unsigned int*)addr, __float_as_uint(v));
}
__device__ __forceinline__ uint32_t pack2h(float lo, float hi) {
    __half2 h = __floats2half2_rn(lo, hi);
    return *(uint32_t*)&h;
}

__device__ __forceinline__ void mma16(float* d, const uint32_t* a, uint32_t b0, uint32_t b1) {
    asm volatile(
        "mma.sync.aligned.m16n8k16.row.col.f32.f16.f16.f32 "
        "{%0,%1,%2,%3}, {%4,%5,%6,%7}, {%8,%9}, {%0,%1,%2,%3};"
        : "+f"(d[0]), "+f"(d[1]), "+f"(d[2]), "+f"(d[3])
        : "r"(a[0]), "r"(a[1]), "r"(a[2]), "r"(a[3]), "r"(b0), "r"(b1));
}

// pack [K x N] row-major fp32 weight into fp16 m16n8k16 B-fragment layout.
__device__ __forceinline__ void pack_Bh(__half* fb, const float* __restrict__ W,
                                        int K, int N, int tid, int nthr)
{
    const int NPB = N >> 3;
    for (int idx = tid; idx < K * N; idx += nthr) {
        const int k = idx / N, n = idx - k * N;
        const int lane = ((n & 7) << 2) + ((k & 7) >> 1);
        const int blk  = (k >> 4) * NPB + (n >> 3);
        const int reg  = (k >> 3) & 1;
        const int pos  = k & 1;
        fb[(blk * 32 + lane) * 4 + reg * 2 + pos] = __float2half_rn(W[idx]);
    }
}

// issue gather loads for one tile into registers (latency exposed to caller)
__device__ __forceinline__ void gather_ld(
    const float* __restrict__ nf, const float* __restrict__ ef,
    const int* __restrict__ src, const int* __restrict__ dst,
    int tile, int tid, float4* pv)
{
    const int e_loc = tid >> 3, sub = tid & 7;
    const int e = tile * TILE + e_loc;
    const int s = src[e], d = dst[e];
    const float4* nfs = (const float4*)nf + (size_t)s * 16;
    const float4* nfd = (const float4*)nf + (size_t)d * 16;
    const float4* efe = (const float4*)ef + (size_t)e * 8;
    #pragma unroll
    for (int i = 0; i < 5; i++) {
        const int f = sub * 5 + i;    // 0..39
        if (f < 16)      pv[i] = __ldg(&nfs[f]);
        else if (f < 32) pv[i] = __ldg(&nfd[f - 16]);
        else             pv[i] = __ldg(&efe[f - 32]);
    }
}

// convert + store previously loaded registers into fragment-layout smem
__device__ __forceinline__ void gather_st(uint32_t* sxu, int tid, const float4* pv)
{
    const int e_loc = tid >> 3, sub = tid & 7;
    const int mt = e_loc >> 4;
    const int rr = e_loc & 15;
    const int g = rr & 7, half = rr >> 3;
    #pragma unroll
    for (int i = 0; i < 5; i++) {
        const int f = sub * 5 + i;
        const int kt    = f >> 2;
        const int tg    = (f & 1) * 2;
        const int thalf = (f >> 1) & 1;
        const int base  = (mt * KT1H + kt) * FB + (g * 4 + tg) * 4 + half + 2 * thalf;
        sxu[base]     = pack2h(pv[i].x, pv[i].y);
        sxu[base + 4] = pack2h(pv[i].z, pv[i].w);
    }
}

// ============================================================
// K0: init scratch
// ============================================================
__global__ void init_kernel() {
    int idx = blockIdx.x * blockDim.x + threadIdx.x;
    g_agg[idx] = 0.0f;
    if (idx < NN) {
        g_m[idx] = __int_as_float(0xff800000);
        g_denom[idx] = 0.0f;
    }
}

// ============================================================
// K1: fused edge kernel, persistent, fp16 mma, double-buffered gather
// ============================================================
__global__ __launch_bounds__(NTHR, 1) void edge_fused_kernel(
    const float* __restrict__ nf, const float* __restrict__ ef,
    const int* __restrict__ src, const int* __restrict__ dst,
    const float* __restrict__ We1, const float* __restrict__ be1,
    const float* __restrict__ We2, const float* __restrict__ be2,
    const float* __restrict__ Wa1, const float* __restrict__ ba1,
    const float* __restrict__ Wa2, const float* __restrict__ ba2,
    float* __restrict__ uh_e)
{
    extern __shared__ char smem[];
    uint32_t* sx0  = (uint32_t*)(smem + SM_X0);
    uint32_t* sx1  = (uint32_t*)(smem + SM_X1);
    uint32_t* shu  = (uint32_t*)(smem + SM_H);
    uint32_t* sB1E = (uint32_t*)(smem + SM_B1E);
    uint32_t* sB1A = (uint32_t*)(smem + SM_B1A);
    uint32_t* sB2  = (uint32_t*)(smem + SM_B2);
    float* sbe1  = (float*)(smem + SM_BE1);
    float* sbe2  = (float*)(smem + SM_BE2);
    float* sba1  = (float*)(smem + SM_BA1);
    float* swa2  = (float*)(smem + SM_WA2);
    float* spart = (float*)(smem + SM_PART);

    const int tid = threadIdx.x;
    const int w = tid >> 5, lane = tid & 31;
    const int wm = w & 3, wn = w >> 2;           // 4 m-tiles x 4 n-groups(32 cols)
    const int tig = lane & 3, gid = lane >> 2;

    pack_Bh((__half*)sB1E, We1, EMIN, HID, tid, NTHR);
    pack_Bh((__half*)sB1A, Wa1, EMIN, HID, tid, NTHR);
    pack_Bh((__half*)sB2,  We2, HID, EOUT, tid, NTHR);
    if (tid < 128) { sbe1[tid] = be1[tid]; sba1[tid] = ba1[tid]; swa2[tid] = Wa2[tid]; }
    if (tid < 64)  sbe2[tid] = be2[tid];
    const float ba2v = ba2[0];
    __syncthreads();

    // prologue: load first tile into registers
    float4 pv[5];
    if (blockIdx.x < NTILES)
        gather_ld(nf, ef, src, dst, blockIdx.x, tid, pv);

    int buf = 0;
    for (int tile = blockIdx.x; tile < NTILES; tile += gridDim.x) {
        uint32_t* sxu = buf ? sx1 : sx0;

        // ---- publish tile t (convert regs -> smem fragments) ----
        gather_st(sxu, tid, pv);
        __syncthreads();

        // ---- prefetch tile t+grid (latency hidden under layer-1) ----
        const int nt = tile + gridDim.x;
        if (nt < NTILES)
            gather_ld(nf, ef, src, dst, nt, tid, pv);

        // ---- layer 1 (E + A fused), k16 steps ----
        float accE[4][4], accA[4][4];
        #pragma unroll
        for (int ni = 0; ni < 4; ni++)
            #pragma unroll
            for (int c = 0; c < 4; c++) { accE[ni][c] = 0.f; accA[ni][c] = 0.f; }

        #pragma unroll
        for (int kt = 0; kt < KT1H; kt++) {
            uint32_t a[4];
            {
                const uint4 t = *(const uint4*)&sxu[(wm * KT1H + kt) * FB + lane * 4];
                a[0] = t.x; a[1] = t.y; a[2] = t.z; a[3] = t.w;
            }
            #pragma unroll
            for (int ni = 0; ni < 4; ni++) {
                const int n8 = wn * 4 + ni;
                const uint2 bE = *(const uint2*)&sB1E[((kt * 16 + n8) * 32 + lane) * 2];
                mma16(accE[ni], a, bE.x, bE.y);
                const uint2 bA = *(const uint2*)&sB1A[((kt * 16 + n8) * 32 + lane) * 2];
                mma16(accA[ni], a, bA.x, bA.y);
            }
        }

        // ---- epilogue E: relu+bias -> h fragment blocks (fp16) ----
        #pragma unroll
        for (int ni = 0; ni < 4; ni++) {
            const int j0 = wn * 32 + ni * 8 + 2 * tig;
            const int jt = wn * 2 + (ni >> 1);
            const int thalf = ni & 1;
            const float b0 = sbe1[j0], b1 = sbe1[j0 + 1];
            const int base = (wm * JT2H + jt) * FB + (gid * 4 + tig) * 4 + 2 * thalf;
            shu[base]     = pack2h(fmaxf(accE[ni][0] + b0, 0.f), fmaxf(accE[ni][1] + b1, 0.f));
            shu[base + 1] = pack2h(fmaxf(accE[ni][2] + b0, 0.f), fmaxf(accE[ni][3] + b1, 0.f));
        }

        // ---- epilogue A: logit partials ----
        {
            float part[2] = {0.f, 0.f};
            #pragma unroll
            for (int ni = 0; ni < 4; ni++) {
                const int j0 = wn * 32 + ni * 8 + 2 * tig;
                const float w0 = swa2[j0], w1 = swa2[j0 + 1];
                const float b0 = sba1[j0], b1 = sba1[j0 + 1];
                part[0] += fmaxf(accA[ni][0] + b0, 0.f) * w0
                         + fmaxf(accA[ni][1] + b1, 0.f) * w1;
                part[1] += fmaxf(accA[ni][2] + b0, 0.f) * w0
                         + fmaxf(accA[ni][3] + b1, 0.f) * w1;
            }
            #pragma unroll
            for (int h2 = 0; h2 < 2; h2++) {
                float v = part[h2];
                v += __shfl_xor_sync(0xffffffff, v, 1);
                v += __shfl_xor_sync(0xffffffff, v, 2);
                if (tig == 0)
                    spart[wn * 64 + wm * 16 + h2 * 8 + gid] = v;
            }
        }
        __syncthreads();

        // ---- layer 2 (E): [64e x 128k] x [128k x 64n], k16 ----
        float acc2[2][4];
        #pragma unroll
        for (int ni = 0; ni < 2; ni++)
            #pragma unroll
            for (int c = 0; c < 4; c++) acc2[ni][c] = 0.f;

        #pragma unroll
        for (int jt = 0; jt < JT2H; jt++) {
            uint32_t a[4];
            {
                const uint4 t = *(const uint4*)&shu[(wm * JT2H + jt) * FB + lane * 4];
                a[0] = t.x; a[1] = t.y; a[2] = t.z; a[3] = t.w;
            }
            #pragma unroll
            for (int ni = 0; ni < 2; ni++) {
                const int n8 = wn * 2 + ni;
                const uint2 b = *(const uint2*)&sB2[((jt * 8 + n8) * 32 + lane) * 2];
                mma16(acc2[ni], a, b.x, b.y);
            }
        }

        // ---- store uh_e + logits ----
        {
            const int e0 = tile * TILE + wm * 16 + gid;
            #pragma unroll
            for (int ni = 0; ni < 2; ni++) {
                const int o = wn * 16 + ni * 8 + 2 * tig;
                const float b0 = sbe2[o], b1 = sbe2[o + 1];
                float2 v0, v1;
                v0.x = acc2[ni][0] + b0; v0.y = acc2[ni][1] + b1;
                v1.x = acc2[ni][2] + b0; v1.y = acc2[ni][3] + b1;
                *(float2*)&uh_e[(size_t)e0 * EOUT + o] = v0;
                *(float2*)&uh_e[(size_t)(e0 + 8) * EOUT + o] = v1;
            }
        }
        if (tid < TILE) {
            const int e = tile * TILE + tid;
            const float logit = spart[tid] + spart[64 + tid]
                              + spart[128 + tid] + spart[192 + tid] + ba2v;
            g_logits[e] = logit;
            atomicMaxFloat(&g_m[dst[e]], logit);
        }
        buf ^= 1;
    }
}

// ============================================================
// K2: ex = exp(logit - m[dst]); denom[dst] += ex
// ============================================================
__global__ void softmax_kernel(const int* __restrict__ dst) {
    int e = blockIdx.x * blockDim.x + threadIdx.x;
    int d = dst[e];
    float ex = expf(g_logits[e] - g_m[d]);
    g_ex[e] = ex;
    atomicAdd(&g_denom[d], ex);
}

// ============================================================
// K3: agg[dst] += uh_e * attn (vector red.v4)
// ============================================================
__global__ void agg_kernel(const int* __restrict__ dst,
                           const float* __restrict__ uh_e) {
    size_t idx = (size_t)blockIdx.x * blockDim.x + threadIdx.x;
    int e  = (int)(idx >> 4);
    int jq = (int)(idx & 15);
    int d  = dst[e];
    float w = g_ex[e] / fmaxf(g_denom[d], 1e-38f);
    float4 v = __ldg((const float4*)uh_e + (size_t)e * 16 + jq);
    v.x *= w; v.y *= w; v.z *= w; v.w *= w;
    float* p = &g_agg[(size_t)d * EOUT + jq * 4];
    asm volatile("red.global.add.v4.f32 [%0], {%1, %2, %3, %4};"
                 :: "l"(p), "f"(v.x), "f"(v.y), "f"(v.z), "f"(v.w) : "memory");
}

// ============================================================
// K4: node MLP (scalar f32x2 path, known good)
// ============================================================
__global__ __launch_bounds__(128) void node_kernel(
    const float* __restrict__ nf,
    const float* __restrict__ Wn1, const float* __restrict__ bn1,
    const float* __restrict__ Wn2, const float* __restrict__ bn2,
    float* __restrict__ uh_n)
{
    __shared__ float s_x[NMIN * PITCH];

    const int tid = threadIdx.x;
    const int n0  = blockIdx.x * TE;

    {
        const int e  = tid & 31;
        const int kq = tid >> 5;
        const int n  = n0 + e;
        const bool ok = (n < NN);
        const float4* ag4 = (const float4*)g_agg;
        const float4* nf4 = (const float4*)nf;
        #pragma unroll
        for (int kk = kq; kk < 32; kk += 4) {
            float4 v = make_float4(0.f, 0.f, 0.f, 0.f);
            if (ok) {
                if (kk < 16) v = ag4[(size_t)n * 16 + kk];
                else         v = nf4[(size_t)n * 16 + (kk - 16)];
            }
            const int k = kk * 4;
            s_x[(k + 0) * PITCH + e] = v.x;
            s_x[(k + 1) * PITCH + e] = v.y;
            s_x[(k + 2) * PITCH + e] = v.z;
            s_x[(k + 3) * PITCH + e] = v.w;
        }
    }
    __syncthreads();

    F2 h[16];
    {
        float b = bn1[tid];
        #pragma unroll
        for (int i = 0; i < 16; i++) h[i].f = make_float2(b, b);
    }
    #pragma unroll 2
    for (int k = 0; k < NMIN; k++) {
        const float w1 = __ldg(&Wn1[k * HID + tid]);
        F2 w; w.f = make_float2(w1, w1);
        const float* row = &s_x[k * PITCH];
        #pragma unroll
        for (int i = 0; i < 16; i++) {
            F2 x; x.f = *(const float2*)&row[2 * i];
            fma2(h[i], x, w);
        }
    }
    __syncthreads();
    float* s_h = s_x;
    #pragma unroll
    for (int i = 0; i < 16; i++) {
        float2 v = h[i].f;
        v.x = fmaxf(v.x, 0.0f); v.y = fmaxf(v.y, 0.0f);
        *(float2*)&s_h[tid * PITCH + 2 * i] = v;
    }
    __syncthreads();

    {
        const int o     = tid & 63;
        const int half  = tid >> 6;
        const int ebase = half * 16;
        F2 acc[8];
        const float b2 = bn2[o];
        #pragma unroll
        for (int i = 0; i < 8; i++) acc[i].f = make_float2(b2, b2);

        #pragma unroll 2
        for (int j = 0; j < HID; j++) {
            const float w = __ldg(&Wn2[j * DOUT + o]);
            F2 w2; w2.f = make_float2(w, w);
            const float* row = &s_h[j * PITCH + ebase];
            #pragma unroll
            for (int i = 0; i < 8; i++) {
                F2 x; x.f = *(const float2*)&row[2 * i];
                fma2(acc[i], x, w2);
            }
        }
        #pragma unroll
        for (int i = 0; i < 8; i++) {
            int na = n0 + ebase + 2 * i;
            int nb = na + 1;
            if (na < NN) uh_n[(size_t)na * DOUT + o] = acc[i].f.x;
            if (nb < NN) uh_n[(size_t)nb * DOUT + o] = acc[i].f.y;
        }
    }
}

// ============================================================
extern "C" void kernel_launch(void* const* d_in, const int* in_sizes, int n_in,
                              void* d_out, int out_size) {
    const float* nf  = (const float*)d_in[0];
    const float* ef  = (const float*)d_in[1];
    const int*   src = (const int*)d_in[2];
    const int*   dst = (const int*)d_in[3];
    const float* We1 = (const float*)d_in[4];
    const float* be1 = (const float*)d_in[5];
    const float* We2 = (const float*)d_in[6];
    const float* be2 = (const float*)d_in[7];
    const float* Wa1 = (const float*)d_in[8];
    const float* ba1 = (const float*)d_in[9];
    const float* Wa2 = (const float*)d_in[10];
    const float* ba2 = (const float*)d_in[11];
    const float* Wn1 = (const float*)d_in[12];
    const float* bn1 = (const float*)d_in[13];
    const float* Wn2 = (const float*)d_in[14];
    const float* bn2 = (const float*)d_in[15];

    float* out  = (float*)d_out;
    float* uh_n = out;
    float* uh_e = out + (size_t)NN * DOUT;

    static bool attr_set = false;
    if (!attr_set) {
        cudaFuncSetAttribute(edge_fused_kernel,
                             cudaFuncAttributeMaxDynamicSharedMemorySize, SMEM_F);
        attr_set = true;
    }

    init_kernel<<<(NN * 64) / 256, 256>>>();
    edge_fused_kernel<<<GRID_P, NTHR, SMEM_F>>>(nf, ef, src, dst,
                                                We1, be1, We2, be2,
                                                Wa1, ba1, Wa2, ba2, uh_e);
    softmax_kernel<<<E_TOTAL / 256, 256>>>(dst);
    agg_kernel<<<(E_TOTAL * 16) / 256, 256>>>(dst, uh_e);
    node_kernel<<<(NN + TE - 1) / TE, 128>>>(nf, Wn1, bn1, Wn2, bn2, uh_n);
}

// round 14
// speedup vs baseline: 1.6075x; 1.0237x over previous
#include <cuda_runtime.h>
#include <cuda_fp16.h>
#include <math.h>
#include <stdint.h>

// ----- problem constants -----
#define E_TOTAL 800000
#define NN      50000
#define DIN     64
#define EIN     32
#define EMIN    160
#define HID     128
#define EOUT    64
#define NMIN    128
#define DOUT    64

#define TILE    64
#define NTILES  (E_TOTAL / TILE)   // 12500
#define GRID_P  148
#define NTHR    256

#define TE      32
#define PITCH   34

// fp16 fragment tiling
#define FB      132     // b32 words per (mt,kt) fragment block (528B)
#define KT1H    10      // layer-1 k16-tiles (160/16)
#define JT2H    8       // layer-2 k16-tiles (128/16)
#define MT      4       // 64 rows / 16

// ----- scratch -----
__device__ float g_logits[E_TOTAL];
__device__ float g_ex[E_TOTAL];
__device__ float g_m[NN];
__device__ float g_denom[NN];
__device__ float g_agg[(size_t)NN * EOUT];

// ----- smem layout (bytes) -----
#define XBYTES   (MT * KT1H * FB * 4)            // 21120
#define SM_X0    0
#define SM_X1    XBYTES                          // 21120
#define SM_H     (2 * XBYTES)                    // 42240
#define SM_B1E   (SM_H + MT * JT2H * FB * 4)     // 42240+16896=59136
#define SM_B1A   (SM_B1E + KT1H * 16 * 64 * 4)   // +40960 = 100096
#define SM_B2    (SM_B1A + KT1H * 16 * 64 * 4)   // +40960 = 141056
#define SM_BE1   (SM_B2 + JT2H * 8 * 64 * 4)     // +16384 = 157440
#define SM_BE2   (SM_BE1 + 512)
#define SM_BA1   (SM_BE2 + 256)
#define SM_WA2   (SM_BA1 + 512)
#define SM_PART  (SM_WA2 + 512)
#define SMEM_F   (SM_PART + 1024)                // 160256

// ============================================================ helpers
union F2 { float2 f; unsigned long long u; };
__device__ __forceinline__ void fma2(F2& acc, F2 x, F2 w) {
    asm("fma.rn.f32x2 %0, %1, %2, %0;" : "+l"(acc.u) : "l"(x.u), "l"(w.u));
}
__device__ __forceinline__ void atomicMaxFloat(float* addr, float v) {
    if (v >= 0.0f) atomicMax((int*)addr, __float_as_int(v));
    else           atomicMin((unsigned int*)addr, __float_as_uint(v));
}
__device__ __forceinline__ uint32_t pack2h(float lo, float hi) {
    __half2 h = __floats2half2_rn(lo, hi);
    return *(uint32_t*)&h;
}

__device__ __forceinline__ void mma16(float* d, const uint32_t* a, uint32_t b0, uint32_t b1) {
    asm volatile(
        "mma.sync.aligned.m16n8k16.row.col.f32.f16.f16.f32 "
        "{%0,%1,%2,%3}, {%4,%5,%6,%7}, {%8,%9}, {%0,%1,%2,%3};"
        : "+f"(d[0]), "+f"(d[1]), "+f"(d[2]), "+f"(d[3])
        : "r"(a[0]), "r"(a[1]), "r"(a[2]), "r"(a[3]), "r"(b0), "r"(b1));
}

// pack [K x N] row-major fp32 weight into fp16 m16n8k16 B-fragment layout.
__device__ __forceinline__ void pack_Bh(__half* fb, const float* __restrict__ W,
                                        int K, int N, int tid, int nthr)
{
    const int NPB = N >> 3;
    for (int idx = tid; idx < K * N; idx += nthr) {
        const int k = idx / N, n = idx - k * N;
        const int lane = ((n & 7) << 2) + ((k & 7) >> 1);
        const int blk  = (k >> 4) * NPB + (n >> 3);
        const int reg  = (k >> 3) & 1;
        const int pos  = k & 1;
        fb[(blk * 32 + lane) * 4 + reg * 2 + pos] = __float2half_rn(W[idx]);
    }
}

// issue gather loads for one tile into registers (4 threads/edge, 10 float4)
__device__ __forceinline__ void gather_ld(
    const float* __restrict__ nf, const float* __restrict__ ef,
    const int* __restrict__ src, const int* __restrict__ dst,
    int tile, int tid, float4* pv)
{
    const int e_loc = tid >> 2, sub = tid & 3;
    const int e = tile * TILE + e_loc;
    const int s = src[e], d = dst[e];
    const float4* nfs = (const float4*)nf + (size_t)s * 16;
    const float4* nfd = (const float4*)nf + (size_t)d * 16;
    const float4* efe = (const float4*)ef + (size_t)e * 8;
    #pragma unroll
    for (int i = 0; i < 10; i++) {
        const int f = sub * 10 + i;    // 0..39
        if (f < 16)      pv[i] = __ldg(&nfs[f]);
        else if (f < 32) pv[i] = __ldg(&nfd[f - 16]);
        else             pv[i] = __ldg(&efe[f - 32]);
    }
}

// convert + store previously loaded registers into fragment-layout smem
__device__ __forceinline__ void gather_st(uint32_t* sxu, int tid, const float4* pv)
{
    const int e_loc = tid >> 2, sub = tid & 3;
    const int mt = e_loc >> 4;
    const int rr = e_loc & 15;
    const int g = rr & 7, half = rr >> 3;
    #pragma unroll
    for (int i = 0; i < 10; i++) {
        const int f = sub * 10 + i;
        const int kt    = f >> 2;
        const int tg    = (f & 1) * 2;
        const int thalf = (f >> 1) & 1;
        const int base  = (mt * KT1H + kt) * FB + (g * 4 + tg) * 4 + half + 2 * thalf;
        sxu[base]     = pack2h(pv[i].x, pv[i].y);
        sxu[base + 4] = pack2h(pv[i].z, pv[i].w);
    }
}

// ============================================================
// K0: init scratch
// ============================================================
__global__ void init_kernel() {
    int idx = blockIdx.x * blockDim.x + threadIdx.x;
    g_agg[idx] = 0.0f;
    if (idx < NN) {
        g_m[idx] = __int_as_float(0xff800000);
        g_denom[idx] = 0.0f;
    }
}

// ============================================================
// K1: fused edge kernel, persistent, fp16 mma, 8 warps, 2 m-tiles/warp
// ============================================================
__global__ __launch_bounds__(NTHR, 1) void edge_fused_kernel(
    const float* __restrict__ nf, const float* __restrict__ ef,
    const int* __restrict__ src, const int* __restrict__ dst,
    const float* __restrict__ We1, const float* __restrict__ be1,
    const float* __restrict__ We2, const float* __restrict__ be2,
    const float* __restrict__ Wa1, const float* __restrict__ ba1,
    const float* __restrict__ Wa2, const float* __restrict__ ba2,
    float* __restrict__ uh_e)
{
    extern __shared__ char smem[];
    uint32_t* sx0  = (uint32_t*)(smem + SM_X0);
    uint32_t* sx1  = (uint32_t*)(smem + SM_X1);
    uint32_t* shu  = (uint32_t*)(smem + SM_H);
    uint32_t* sB1E = (uint32_t*)(smem + SM_B1E);
    uint32_t* sB1A = (uint32_t*)(smem + SM_B1A);
    uint32_t* sB2  = (uint32_t*)(smem + SM_B2);
    float* sbe1  = (float*)(smem + SM_BE1);
    float* sbe2  = (float*)(smem + SM_BE2);
    float* sba1  = (float*)(smem + SM_BA1);
    float* swa2  = (float*)(smem + SM_WA2);
    float* spart = (float*)(smem + SM_PART);

    const int tid = threadIdx.x;
    const int w = tid >> 5, lane = tid & 31;
    const int wm = w & 1, wn = w >> 1;           // 2 m-pairs x 4 n-groups
    const int tig = lane & 3, gid = lane >> 2;

    pack_Bh((__half*)sB1E, We1, EMIN, HID, tid, NTHR);
    pack_Bh((__half*)sB1A, Wa1, EMIN, HID, tid, NTHR);
    pack_Bh((__half*)sB2,  We2, HID, EOUT, tid, NTHR);
    if (tid < 128) { sbe1[tid] = be1[tid]; sba1[tid] = ba1[tid]; swa2[tid] = Wa2[tid]; }
    if (tid < 64)  sbe2[tid] = be2[tid];
    const float ba2v = ba2[0];
    __syncthreads();

    // prologue: load first tile into registers
    float4 pv[10];
    if (blockIdx.x < NTILES)
        gather_ld(nf, ef, src, dst, blockIdx.x, tid, pv);

    int buf = 0;
    for (int tile = blockIdx.x; tile < NTILES; tile += gridDim.x) {
        uint32_t* sxu = buf ? sx1 : sx0;

        // ---- publish tile t ----
        gather_st(sxu, tid, pv);
        __syncthreads();

        // ---- prefetch tile t+grid (hidden under layer-1) ----
        const int nt = tile + gridDim.x;
        if (nt < NTILES)
            gather_ld(nf, ef, src, dst, nt, tid, pv);

        // ---- layer 1 (E + A fused), 2 m-tiles per warp ----
        float accE[2][4][4], accA[2][4][4];
        #pragma unroll
        for (int mi = 0; mi < 2; mi++)
            #pragma unroll
            for (int ni = 0; ni < 4; ni++)
                #pragma unroll
                for (int c = 0; c < 4; c++) { accE[mi][ni][c] = 0.f; accA[mi][ni][c] = 0.f; }

        #pragma unroll
        for (int kt = 0; kt < KT1H; kt++) {
            uint32_t a[2][4];
            #pragma unroll
            for (int mi = 0; mi < 2; mi++) {
                const uint4 t = *(const uint4*)&sxu[((wm * 2 + mi) * KT1H + kt) * FB + lane * 4];
                a[mi][0] = t.x; a[mi][1] = t.y; a[mi][2] = t.z; a[mi][3] = t.w;
            }
            #pragma unroll
            for (int ni = 0; ni < 4; ni++) {
                const int n8 = wn * 4 + ni;
                const uint2 bE = *(const uint2*)&sB1E[((kt * 16 + n8) * 32 + lane) * 2];
                mma16(accE[0][ni], a[0], bE.x, bE.y);
                mma16(accE[1][ni], a[1], bE.x, bE.y);
                const uint2 bA = *(const uint2*)&sB1A[((kt * 16 + n8) * 32 + lane) * 2];
                mma16(accA[0][ni], a[0], bA.x, bA.y);
                mma16(accA[1][ni], a[1], bA.x, bA.y);
            }
        }

        // ---- epilogue E: relu+bias -> h fragment blocks (fp16) ----
        #pragma unroll
        for (int mi = 0; mi < 2; mi++) {
            const int mt = wm * 2 + mi;
            #pragma unroll
            for (int ni = 0; ni < 4; ni++) {
                const int j0 = wn * 32 + ni * 8 + 2 * tig;
                const int jt = wn * 2 + (ni >> 1);
                const int thalf = ni & 1;
                const float b0 = sbe1[j0], b1 = sbe1[j0 + 1];
                const int base = (mt * JT2H + jt) * FB + (gid * 4 + tig) * 4 + 2 * thalf;
                shu[base]     = pack2h(fmaxf(accE[mi][ni][0] + b0, 0.f),
                                       fmaxf(accE[mi][ni][1] + b1, 0.f));
                shu[base + 1] = pack2h(fmaxf(accE[mi][ni][2] + b0, 0.f),
                                       fmaxf(accE[mi][ni][3] + b1, 0.f));
            }
        }

        // ---- epilogue A: logit partials ----
        #pragma unroll
        for (int mi = 0; mi < 2; mi++) {
            const int mt = wm * 2 + mi;
            float part[2] = {0.f, 0.f};
            #pragma unroll
            for (int ni = 0; ni < 4; ni++) {
                const int j0 = wn * 32 + ni * 8 + 2 * tig;
                const float w0 = swa2[j0], w1 = swa2[j0 + 1];
                const float b0 = sba1[j0], b1 = sba1[j0 + 1];
                part[0] += fmaxf(accA[mi][ni][0] + b0, 0.f) * w0
                         + fmaxf(accA[mi][ni][1] + b1, 0.f) * w1;
                part[1] += fmaxf(accA[mi][ni][2] + b0, 0.f) * w0
                         + fmaxf(accA[mi][ni][3] + b1, 0.f) * w1;
            }
            #pragma unroll
            for (int h2 = 0; h2 < 2; h2++) {
                float v = part[h2];
                v += __shfl_xor_sync(0xffffffff, v, 1);
                v += __shfl_xor_sync(0xffffffff, v, 2);
                if (tig == 0)
                    spart[wn * 64 + mt * 16 + h2 * 8 + gid] = v;
            }
        }
        __syncthreads();

        // ---- layer 2 (E): [64e x 128k] x [128k x 64n], k16 ----
        float acc2[2][2][4];
        #pragma unroll
        for (int mi = 0; mi < 2; mi++)
            #pragma unroll
            for (int ni = 0; ni < 2; ni++)
                #pragma unroll
                for (int c = 0; c < 4; c++) acc2[mi][ni][c] = 0.f;

        #pragma unroll
        for (int jt = 0; jt < JT2H; jt++) {
            uint32_t a[2][4];
            #pragma unroll
            for (int mi = 0; mi < 2; mi++) {
                const uint4 t = *(const uint4*)&shu[((wm * 2 + mi) * JT2H + jt) * FB + lane * 4];
                a[mi][0] = t.x; a[mi][1] = t.y; a[mi][2] = t.z; a[mi][3] = t.w;
            }
            #pragma unroll
            for (int ni = 0; ni < 2; ni++) {
                const int n8 = wn * 2 + ni;
                const uint2 b = *(const uint2*)&sB2[((jt * 8 + n8) * 32 + lane) * 2];
                mma16(acc2[0][ni], a[0], b.x, b.y);
                mma16(acc2[1][ni], a[1], b.x, b.y);
            }
        }

        // ---- store uh_e + logits ----
        #pragma unroll
        for (int mi = 0; mi < 2; mi++) {
            const int e0 = tile * TILE + (wm * 2 + mi) * 16 + gid;
            #pragma unroll
            for (int ni = 0; ni < 2; ni++) {
                const int o = wn * 16 + ni * 8 + 2 * tig;
                const float b0 = sbe2[o], b1 = sbe2[o + 1];
                float2 v0, v1;
                v0.x = acc2[mi][ni][0] + b0; v0.y = acc2[mi][ni][1] + b1;
                v1.x = acc2[mi][ni][2] + b0; v1.y = acc2[mi][ni][3] + b1;
                *(float2*)&uh_e[(size_t)e0 * EOUT + o] = v0;
                *(float2*)&uh_e[(size_t)(e0 + 8) * EOUT + o] = v1;
            }
        }
        if (tid < TILE) {
            const int e = tile * TILE + tid;
            const float logit = spart[tid] + spart[64 + tid]
                              + spart[128 + tid] + spart[192 + tid] + ba2v;
            g_logits[e] = logit;
            atomicMaxFloat(&g_m[dst[e]], logit);
        }
        buf ^= 1;
    }
}

// ============================================================
// K2: ex = exp(logit - m[dst]); denom[dst] += ex
// ============================================================
__global__ void softmax_kernel(const int* __restrict__ dst) {
    int e = blockIdx.x * blockDim.x + threadIdx.x;
    int d = dst[e];
    float ex = expf(g_logits[e] - g_m[d]);
    g_ex[e] = ex;
    atomicAdd(&g_denom[d], ex);
}

// ============================================================
// K3: agg[dst] += uh_e * attn (vector red.v4)
// ============================================================
__global__ void agg_kernel(const int* __restrict__ dst,
                           const float* __restrict__ uh_e) {
    size_t idx = (size_t)blockIdx.x * blockDim.x + threadIdx.x;
    int e  = (int)(idx >> 4);
    int jq = (int)(idx & 15);
    int d  = dst[e];
    float w = g_ex[e] / fmaxf(g_denom[d], 1e-38f);
    float4 v = __ldg((const float4*)uh_e + (size_t)e * 16 + jq);
    v.x *= w; v.y *= w; v.z *= w; v.w *= w;
    float* p = &g_agg[(size_t)d * EOUT + jq * 4];
    asm volatile("red.global.add.v4.f32 [%0], {%1, %2, %3, %4};"
                 :: "l"(p), "f"(v.x), "f"(v.y), "f"(v.z), "f"(v.w) : "memory");
}

// ============================================================
// K4: node MLP (scalar f32x2 path, known good)
// ============================================================
__global__ __launch_bounds__(128) void node_kernel(
    const float* __restrict__ nf,
    const float* __restrict__ Wn1, const float* __restrict__ bn1,
    const float* __restrict__ Wn2, const float* __restrict__ bn2,
    float* __restrict__ uh_n)
{
    __shared__ float s_x[NMIN * PITCH];

    const int tid = threadIdx.x;
    const int n0  = blockIdx.x * TE;

    {
        const int e  = tid & 31;
        const int kq = tid >> 5;
        const int n  = n0 + e;
        const bool ok = (n < NN);
        const float4* ag4 = (const float4*)g_agg;
        const float4* nf4 = (const float4*)nf;
        #pragma unroll
        for (int kk = kq; kk < 32; kk += 4) {
            float4 v = make_float4(0.f, 0.f, 0.f, 0.f);
            if (ok) {
                if (kk < 16) v = ag4[(size_t)n * 16 + kk];
                else         v = nf4[(size_t)n * 16 + (kk - 16)];
            }
            const int k = kk * 4;
            s_x[(k + 0) * PITCH + e] = v.x;
            s_x[(k + 1) * PITCH + e] = v.y;
            s_x[(k + 2) * PITCH + e] = v.z;
            s_x[(k + 3) * PITCH + e] = v.w;
        }
    }
    __syncthreads();

    F2 h[16];
    {
        float b = bn1[tid];
        #pragma unroll
        for (int i = 0; i < 16; i++) h[i].f = make_float2(b, b);
    }
    #pragma unroll 2
    for (int k = 0; k < NMIN; k++) {
        const float w1 = __ldg(&Wn1[k * HID + tid]);
        F2 w; w.f = make_float2(w1, w1);
        const float* row = &s_x[k * PITCH];
        #pragma unroll
        for (int i = 0; i < 16; i++) {
            F2 x; x.f = *(const float2*)&row[2 * i];
            fma2(h[i], x, w);
        }
    }
    __syncthreads();
    float* s_h = s_x;
    #pragma unroll
    for (int i = 0; i < 16; i++) {
        float2 v = h[i].f;
        v.x = fmaxf(v.x, 0.0f); v.y = fmaxf(v.y, 0.0f);
        *(float2*)&s_h[tid * PITCH + 2 * i] = v;
    }
    __syncthreads();

    {
        const int o     = tid & 63;
        const int half  = tid >> 6;
        const int ebase = half * 16;
        F2 acc[8];
        const float b2 = bn2[o];
        #pragma unroll
        for (int i = 0; i < 8; i++) acc[i].f = make_float2(b2, b2);

        #pragma unroll 2
        for (int j = 0; j < HID; j++) {
            const float w = __ldg(&Wn2[j * DOUT + o]);
            F2 w2; w2.f = make_float2(w, w);
            const float* row = &s_h[j * PITCH + ebase];
            #pragma unroll
            for (int i = 0; i < 8; i++) {
                F2 x; x.f = *(const float2*)&row[2 * i];
                fma2(acc[i], x, w2);
            }
        }
        #pragma unroll
        for (int i = 0; i < 8; i++) {
            int na = n0 + ebase + 2 * i;
            int nb = na + 1;
            if (na < NN) uh_n[(size_t)na * DOUT + o] = acc[i].f.x;
            if (nb < NN) uh_n[(size_t)nb * DOUT + o] = acc[i].f.y;
        }
    }
}

// ============================================================
extern "C" void kernel_launch(void* const* d_in, const int* in_sizes, int n_in,
                              void* d_out, int out_size) {
    const float* nf  = (const float*)d_in[0];
    const float* ef  = (const float*)d_in[1];
    const int*   src = (const int*)d_in[2];
    const int*   dst = (const int*)d_in[3];
    const float* We1 = (const float*)d_in[4];
    const float* be1 = (const float*)d_in[5];
    const float* We2 = (const float*)d_in[6];
    const float* be2 = (const float*)d_in[7];
    const float* Wa1 = (const float*)d_in[8];
    const float* ba1 = (const float*)d_in[9];
    const float* Wa2 = (const float*)d_in[10];
    const float* ba2 = (const float*)d_in[11];
    const float* Wn1 = (const float*)d_in[12];
    const float* bn1 = (const float*)d_in[13];
    const float* Wn2 = (const float*)d_in[14];
    const float* bn2 = (const float*)d_in[15];

    float* out  = (float*)d_out;
    float* uh_n = out;
    float* uh_e = out + (size_t)NN * DOUT;

    static bool attr_set = false;
    if (!attr_set) {
        cudaFuncSetAttribute(edge_fused_kernel,
                             cudaFuncAttributeMaxDynamicSharedMemorySize, SMEM_F);
        attr_set = true;
    }

    init_kernel<<<(NN * 64) / 256, 256>>>();
    edge_fused_kernel<<<GRID_P, NTHR, SMEM_F>>>(nf, ef, src, dst,
                                                We1, be1, We2, be2,
                                                Wa1, ba1, Wa2, ba2, uh_e);
    softmax_kernel<<<E_TOTAL / 256, 256>>>(dst);
    agg_kernel<<<(E_TOTAL * 16) / 256, 256>>>(dst, uh_e);
    node_kernel<<<(NN + TE - 1) / TE, 128>>>(nf, Wn1, bn1, Wn2, bn2, uh_n);
}

// round 15
// speedup vs baseline: 1.6638x; 1.0351x over previous
#include <cuda_runtime.h>
#include <cuda_fp16.h>
#include <math.h>
#include <stdint.h>

// ----- problem constants -----
#define E_TOTAL 800000
#define NN      50000
#define DIN     64
#define EIN     32
#define EMIN    160
#define HID     128
#define EOUT    64
#define NMIN    128
#define DOUT    64

#define TILE    64
#define NTILES  (E_TOTAL / TILE)   // 12500
#define GRID_P  148
#define NTHR    256

#define TE      32
#define PITCH   34

// fp16 fragment tiling
#define FB      132     // b32 words per (mt,kt) fragment block (528B)
#define KT1H    10      // layer-1 k16-tiles (160/16)
#define JT2H    8       // layer-2 k16-tiles (128/16)
#define MT      4       // 64 rows / 16

// ----- scratch -----
__device__ float g_denom[NN];
__device__ float g_agg[(size_t)NN * EOUT];

// ----- smem layout (bytes) -----
#define XBYTES   (MT * KT1H * FB * 4)            // 21120
#define SM_X0    0
#define SM_X1    XBYTES                          // 21120
#define SM_H     (2 * XBYTES)                    // 42240
#define SM_B1E   (SM_H + MT * JT2H * FB * 4)     // 42240+16896=59136
#define SM_B1A   (SM_B1E + KT1H * 16 * 64 * 4)   // +40960 = 100096
#define SM_B2    (SM_B1A + KT1H * 16 * 64 * 4)   // +40960 = 141056
#define SM_BE1   (SM_B2 + JT2H * 8 * 64 * 4)     // +16384 = 157440
#define SM_BE2   (SM_BE1 + 512)
#define SM_BA1   (SM_BE2 + 256)
#define SM_WA2   (SM_BA1 + 512)
#define SM_PART  (SM_WA2 + 512)
#define SM_SEX   (SM_PART + 1024)                // 64 floats: per-edge exp
#define SM_SDST  (SM_SEX + 256)                  // 64 ints: per-edge dst
#define SMEM_F   (SM_SDST + 256)                 // 161792

// ============================================================ helpers
union F2 { float2 f; unsigned long long u; };
__device__ __forceinline__ void fma2(F2& acc, F2 x, F2 w) {
    asm("fma.rn.f32x2 %0, %1, %2, %0;" : "+l"(acc.u) : "l"(x.u), "l"(w.u));
}
__device__ __forceinline__ uint32_t pack2h(float lo, float hi) {
    __half2 h = __floats2half2_rn(lo, hi);
    return *(uint32_t*)&h;
}

__device__ __forceinline__ void mma16(float* d, const uint32_t* a, uint32_t b0, uint32_t b1) {
    asm volatile(
        "mma.sync.aligned.m16n8k16.row.col.f32.f16.f16.f32 "
        "{%0,%1,%2,%3}, {%4,%5,%6,%7}, {%8,%9}, {%0,%1,%2,%3};"
        : "+f"(d[0]), "+f"(d[1]), "+f"(d[2]), "+f"(d[3])
        : "r"(a[0]), "r"(a[1]), "r"(a[2]), "r"(a[3]), "r"(b0), "r"(b1));
}

__device__ __forceinline__ void redv2(float* p, float x, float y) {
    asm volatile("red.global.add.v2.f32 [%0], {%1, %2};"
                 :: "l"(p), "f"(x), "f"(y) : "memory");
}

// pack [K x N] row-major fp32 weight into fp16 m16n8k16 B-fragment layout.
__device__ __forceinline__ void pack_Bh(__half* fb, const float* __restrict__ W,
                                        int K, int N, int tid, int nthr)
{
    const int NPB = N >> 3;
    for (int idx = tid; idx < K * N; idx += nthr) {
        const int k = idx / N, n = idx - k * N;
        const int lane = ((n & 7) << 2) + ((k & 7) >> 1);
        const int blk  = (k >> 4) * NPB + (n >> 3);
        const int reg  = (k >> 3) & 1;
        const int pos  = k & 1;
        fb[(blk * 32 + lane) * 4 + reg * 2 + pos] = __float2half_rn(W[idx]);
    }
}

// issue gather loads for one tile into registers (4 threads/edge, 10 float4)
__device__ __forceinline__ void gather_ld(
    const float* __restrict__ nf, const float* __restrict__ ef,
    const int* __restrict__ src, const int* __restrict__ dst,
    int tile, int tid, float4* pv, int* pd)
{
    const int e_loc = tid >> 2, sub = tid & 3;
    const int e = tile * TILE + e_loc;
    const int s = src[e], d = dst[e];
    *pd = d;
    const float4* nfs = (const float4*)nf + (size_t)s * 16;
    const float4* nfd = (const float4*)nf + (size_t)d * 16;
    const float4* efe = (const float4*)ef + (size_t)e * 8;
    #pragma unroll
    for (int i = 0; i < 10; i++) {
        const int f = sub * 10 + i;    // 0..39
        if (f < 16)      pv[i] = __ldg(&nfs[f]);
        else if (f < 32) pv[i] = __ldg(&nfd[f - 16]);
        else             pv[i] = __ldg(&efe[f - 32]);
    }
}

// convert + store previously loaded registers into fragment-layout smem
__device__ __forceinline__ void gather_st(uint32_t* sxu, int* sdst, int tid,
                                          const float4* pv, int pd)
{
    const int e_loc = tid >> 2, sub = tid & 3;
    const int mt = e_loc >> 4;
    const int rr = e_loc & 15;
    const int g = rr & 7, half = rr >> 3;
    if (sub == 0) sdst[e_loc] = pd;
    #pragma unroll
    for (int i = 0; i < 10; i++) {
        const int f = sub * 10 + i;
        const int kt    = f >> 2;
        const int tg    = (f & 1) * 2;
        const int thalf = (f >> 1) & 1;
        const int base  = (mt * KT1H + kt) * FB + (g * 4 + tg) * 4 + half + 2 * thalf;
        sxu[base]     = pack2h(pv[i].x, pv[i].y);
        sxu[base + 4] = pack2h(pv[i].z, pv[i].w);
    }
}

// ============================================================
// K0: init scratch
// ============================================================
__global__ void init_kernel() {
    int idx = blockIdx.x * blockDim.x + threadIdx.x;
    g_agg[idx] = 0.0f;
    if (idx < NN) g_denom[idx] = 0.0f;
}

// ============================================================
// K1: fused edge kernel: E-MLP + A-MLP + softmax-exp + scatter-agg
// ============================================================
__global__ __launch_bounds__(NTHR, 1) void edge_fused_kernel(
    const float* __restrict__ nf, const float* __restrict__ ef,
    const int* __restrict__ src, const int* __restrict__ dst,
    const float* __restrict__ We1, const float* __restrict__ be1,
    const float* __restrict__ We2, const float* __restrict__ be2,
    const float* __restrict__ Wa1, const float* __restrict__ ba1,
    const float* __restrict__ Wa2, const float* __restrict__ ba2,
    float* __restrict__ uh_e)
{
    extern __shared__ char smem[];
    uint32_t* sx0  = (uint32_t*)(smem + SM_X0);
    uint32_t* sx1  = (uint32_t*)(smem + SM_X1);
    uint32_t* shu  = (uint32_t*)(smem + SM_H);
    uint32_t* sB1E = (uint32_t*)(smem + SM_B1E);
    uint32_t* sB1A = (uint32_t*)(smem + SM_B1A);
    uint32_t* sB2  = (uint32_t*)(smem + SM_B2);
    float* sbe1  = (float*)(smem + SM_BE1);
    float* sbe2  = (float*)(smem + SM_BE2);
    float* sba1  = (float*)(smem + SM_BA1);
    float* swa2  = (float*)(smem + SM_WA2);
    float* spart = (float*)(smem + SM_PART);
    float* sex   = (float*)(smem + SM_SEX);
    int*   sdst  = (int*)(smem + SM_SDST);

    const int tid = threadIdx.x;
    const int w = tid >> 5, lane = tid & 31;
    const int wm = w & 1, wn = w >> 1;           // 2 m-pairs x 4 n-groups
    const int tig = lane & 3, gid = lane >> 2;

    pack_Bh((__half*)sB1E, We1, EMIN, HID, tid, NTHR);
    pack_Bh((__half*)sB1A, Wa1, EMIN, HID, tid, NTHR);
    pack_Bh((__half*)sB2,  We2, HID, EOUT, tid, NTHR);
    if (tid < 128) { sbe1[tid] = be1[tid]; sba1[tid] = ba1[tid]; swa2[tid] = Wa2[tid]; }
    if (tid < 64)  sbe2[tid] = be2[tid];
    const float ba2v = ba2[0];
    __syncthreads();

    // prologue: load first tile into registers
    float4 pv[10];
    int pd = 0;
    if (blockIdx.x < NTILES)
        gather_ld(nf, ef, src, dst, blockIdx.x, tid, pv, &pd);

    int buf = 0;
    for (int tile = blockIdx.x; tile < NTILES; tile += gridDim.x) {
        uint32_t* sxu = buf ? sx1 : sx0;

        // ---- publish tile t ----
        gather_st(sxu, sdst, tid, pv, pd);
        __syncthreads();

        // ---- prefetch tile t+grid (hidden under layer-1) ----
        const int nt = tile + gridDim.x;
        if (nt < NTILES)
            gather_ld(nf, ef, src, dst, nt, tid, pv, &pd);

        // ---- layer 1 (E + A fused), 2 m-tiles per warp ----
        float accE[2][4][4], accA[2][4][4];
        #pragma unroll
        for (int mi = 0; mi < 2; mi++)
            #pragma unroll
            for (int ni = 0; ni < 4; ni++)
                #pragma unroll
                for (int c = 0; c < 4; c++) { accE[mi][ni][c] = 0.f; accA[mi][ni][c] = 0.f; }

        #pragma unroll
        for (int kt = 0; kt < KT1H; kt++) {
            uint32_t a[2][4];
            #pragma unroll
            for (int mi = 0; mi < 2; mi++) {
                const uint4 t = *(const uint4*)&sxu[((wm * 2 + mi) * KT1H + kt) * FB + lane * 4];
                a[mi][0] = t.x; a[mi][1] = t.y; a[mi][2] = t.z; a[mi][3] = t.w;
            }
            #pragma unroll
            for (int ni = 0; ni < 4; ni++) {
                const int n8 = wn * 4 + ni;
                const uint2 bE = *(const uint2*)&sB1E[((kt * 16 + n8) * 32 + lane) * 2];
                mma16(accE[0][ni], a[0], bE.x, bE.y);
                mma16(accE[1][ni], a[1], bE.x, bE.y);
                const uint2 bA = *(const uint2*)&sB1A[((kt * 16 + n8) * 32 + lane) * 2];
                mma16(accA[0][ni], a[0], bA.x, bA.y);
                mma16(accA[1][ni], a[1], bA.x, bA.y);
            }
        }

        // ---- epilogue E: relu+bias -> h fragment blocks (fp16) ----
        #pragma unroll
        for (int mi = 0; mi < 2; mi++) {
            const int mt = wm * 2 + mi;
            #pragma unroll
            for (int ni = 0; ni < 4; ni++) {
                const int j0 = wn * 32 + ni * 8 + 2 * tig;
                const int jt = wn * 2 + (ni >> 1);
                const int thalf = ni & 1;
                const float b0 = sbe1[j0], b1 = sbe1[j0 + 1];
                const int base = (mt * JT2H + jt) * FB + (gid * 4 + tig) * 4 + 2 * thalf;
                shu[base]     = pack2h(fmaxf(accE[mi][ni][0] + b0, 0.f),
                                       fmaxf(accE[mi][ni][1] + b1, 0.f));
                shu[base + 1] = pack2h(fmaxf(accE[mi][ni][2] + b0, 0.f),
                                       fmaxf(accE[mi][ni][3] + b1, 0.f));
            }
        }

        // ---- epilogue A: logit partials ----
        #pragma unroll
        for (int mi = 0; mi < 2; mi++) {
            const int mt = wm * 2 + mi;
            float part[2] = {0.f, 0.f};
            #pragma unroll
            for (int ni = 0; ni < 4; ni++) {
                const int j0 = wn * 32 + ni * 8 + 2 * tig;
                const float w0 = swa2[j0], w1 = swa2[j0 + 1];
                const float b0 = sba1[j0], b1 = sba1[j0 + 1];
                part[0] += fmaxf(accA[mi][ni][0] + b0, 0.f) * w0
                         + fmaxf(accA[mi][ni][1] + b1, 0.f) * w1;
                part[1] += fmaxf(accA[mi][ni][2] + b0, 0.f) * w0
                         + fmaxf(accA[mi][ni][3] + b1, 0.f) * w1;
            }
            #pragma unroll
            for (int h2 = 0; h2 < 2; h2++) {
                float v = part[h2];
                v += __shfl_xor_sync(0xffffffff, v, 1);
                v += __shfl_xor_sync(0xffffffff, v, 2);
                if (tig == 0)
                    spart[wn * 64 + mt * 16 + h2 * 8 + gid] = v;
            }
        }
        __syncthreads();

        // ---- softmax exp (max-free identity) + denom scatter ----
        if (tid < TILE) {
            const float logit = spart[tid] + spart[64 + tid]
                              + spart[128 + tid] + spart[192 + tid] + ba2v;
            const float ex = expf(logit);
            sex[tid] = ex;
            atomicAdd(&g_denom[sdst[tid]], ex);   // compiles to RED.ADD
        }
        __syncthreads();

        // ---- layer 2 (E): [64e x 128k] x [128k x 64n], k16 ----
        float acc2[2][2][4];
        #pragma unroll
        for (int mi = 0; mi < 2; mi++)
            #pragma unroll
            for (int ni = 0; ni < 2; ni++)
                #pragma unroll
                for (int c = 0; c < 4; c++) acc2[mi][ni][c] = 0.f;

        #pragma unroll
        for (int jt = 0; jt < JT2H; jt++) {
            uint32_t a[2][4];
            #pragma unroll
            for (int mi = 0; mi < 2; mi++) {
                const uint4 t = *(const uint4*)&shu[((wm * 2 + mi) * JT2H + jt) * FB + lane * 4];
                a[mi][0] = t.x; a[mi][1] = t.y; a[mi][2] = t.z; a[mi][3] = t.w;
            }
            #pragma unroll
            for (int ni = 0; ni < 2; ni++) {
                const int n8 = wn * 2 + ni;
                const uint2 b = *(const uint2*)&sB2[((jt * 8 + n8) * 32 + lane) * 2];
                mma16(acc2[0][ni], a[0], b.x, b.y);
                mma16(acc2[1][ni], a[1], b.x, b.y);
            }
        }

        // ---- store uh_e + scatter exp-weighted aggregation ----
        #pragma unroll
        for (int mi = 0; mi < 2; mi++) {
            const int le0 = (wm * 2 + mi) * 16 + gid;      // local edge, row gid
            const int e0  = tile * TILE + le0;
            const float w0x = sex[le0];
            const float w1x = sex[le0 + 8];
            const int d0 = sdst[le0];
            const int d1 = sdst[le0 + 8];
            #pragma unroll
            for (int ni = 0; ni < 2; ni++) {
                const int o = wn * 16 + ni * 8 + 2 * tig;
                const float b0 = sbe2[o], b1 = sbe2[o + 1];
                float2 v0, v1;
                v0.x = acc2[mi][ni][0] + b0; v0.y = acc2[mi][ni][1] + b1;
                v1.x = acc2[mi][ni][2] + b0; v1.y = acc2[mi][ni][3] + b1;
                *(float2*)&uh_e[(size_t)e0 * EOUT + o] = v0;
                *(float2*)&uh_e[(size_t)(e0 + 8) * EOUT + o] = v1;
                redv2(&g_agg[(size_t)d0 * EOUT + o], v0.x * w0x, v0.y * w0x);
                redv2(&g_agg[(size_t)d1 * EOUT + o], v1.x * w1x, v1.y * w1x);
            }
        }
        buf ^= 1;
    }
}

// ============================================================
// K4: node MLP on concat(agg/denom, nf)  (scalar f32x2 path)
// ============================================================
__global__ __launch_bounds__(128) void node_kernel(
    const float* __restrict__ nf,
    const float* __restrict__ Wn1, const float* __restrict__ bn1,
    const float* __restrict__ Wn2, const float* __restrict__ bn2,
    float* __restrict__ uh_n)
{
    __shared__ float s_x[NMIN * PITCH];

    const int tid = threadIdx.x;
    const int n0  = blockIdx.x * TE;

    {
        const int e  = tid & 31;
        const int kq = tid >> 5;
        const int n  = n0 + e;
        const bool ok = (n < NN);
        const float4* ag4 = (const float4*)g_agg;
        const float4* nf4 = (const float4*)nf;
        const float rden = ok ? (1.0f / fmaxf(g_denom[n], 1e-38f)) : 0.0f;
        #pragma unroll
        for (int kk = kq; kk < 32; kk += 4) {
            float4 v = make_float4(0.f, 0.f, 0.f, 0.f);
            if (ok) {
                if (kk < 16) {
                    v = ag4[(size_t)n * 16 + kk];
                    v.x *= rden; v.y *= rden; v.z *= rden; v.w *= rden;
                } else {
                    v = nf4[(size_t)n * 16 + (kk - 16)];
                }
            }
            const int k = kk * 4;
            s_x[(k + 0) * PITCH + e] = v.x;
            s_x[(k + 1) * PITCH + e] = v.y;
            s_x[(k + 2) * PITCH + e] = v.z;
            s_x[(k + 3) * PITCH + e] = v.w;
        }
    }
    __syncthreads();

    F2 h[16];
    {
        float b = bn1[tid];
        #pragma unroll
        for (int i = 0; i < 16; i++) h[i].f = make_float2(b, b);
    }
    #pragma unroll 2
    for (int k = 0; k < NMIN; k++) {
        const float w1 = __ldg(&Wn1[k * HID + tid]);
        F2 w; w.f = make_float2(w1, w1);
        const float* row = &s_x[k * PITCH];
        #pragma unroll
        for (int i = 0; i < 16; i++) {
            F2 x; x.f = *(const float2*)&row[2 * i];
            fma2(h[i], x, w);
        }
    }
    __syncthreads();
    float* s_h = s_x;
    #pragma unroll
    for (int i = 0; i < 16; i++) {
        float2 v = h[i].f;
        v.x = fmaxf(v.x, 0.0f); v.y = fmaxf(v.y, 0.0f);
        *(float2*)&s_h[tid * PITCH + 2 * i] = v;
    }
    __syncthreads();

    {
        const int o     = tid & 63;
        const int half  = tid >> 6;
        const int ebase = half * 16;
        F2 acc[8];
        const float b2 = bn2[o];
        #pragma unroll
        for (int i = 0; i < 8; i++) acc[i].f = make_float2(b2, b2);

        #pragma unroll 2
        for (int j = 0; j < HID; j++) {
            const float w = __ldg(&Wn2[j * DOUT + o]);
            F2 w2; w2.f = make_float2(w, w);
            const float* row = &s_h[j * PITCH + ebase];
            #pragma unroll
            for (int i = 0; i < 8; i++) {
                F2 x; x.f = *(const float2*)&row[2 * i];
                fma2(acc[i], x, w2);
            }
        }
        #pragma unroll
        for (int i = 0; i < 8; i++) {
            int na = n0 + ebase + 2 * i;
            int nb = na + 1;
            if (na < NN) uh_n[(size_t)na * DOUT + o] = acc[i].f.x;
            if (nb < NN) uh_n[(size_t)nb * DOUT + o] = acc[i].f.y;
        }
    }
}

// ============================================================
extern "C" void kernel_launch(void* const* d_in, const int* in_sizes, int n_in,
                              void* d_out, int out_size) {
    const float* nf  = (const float*)d_in[0];
    const float* ef  = (const float*)d_in[1];
    const int*   src = (const int*)d_in[2];
    const int*   dst = (const int*)d_in[3];
    const float* We1 = (const float*)d_in[4];
    const float* be1 = (const float*)d_in[5];
    const float* We2 = (const float*)d_in[6];
    const float* be2 = (const float*)d_in[7];
    const float* Wa1 = (const float*)d_in[8];
    const float* ba1 = (const float*)d_in[9];
    const float* Wa2 = (const float*)d_in[10];
    const float* ba2 = (const float*)d_in[11];
    const float* Wn1 = (const float*)d_in[12];
    const float* bn1 = (const float*)d_in[13];
    const float* Wn2 = (const float*)d_in[14];
    const float* bn2 = (const float*)d_in[15];

    float* out  = (float*)d_out;
    float* uh_n = out;
    float* uh_e = out + (size_t)NN * DOUT;

    static bool attr_set = false;
    if (!attr_set) {
        cudaFuncSetAttribute(edge_fused_kernel,
                             cudaFuncAttributeMaxDynamicSharedMemorySize, SMEM_F);
        attr_set = true;
    }

    init_kernel<<<(NN * 64) / 256, 256>>>();
    edge_fused_kernel<<<GRID_P, NTHR, SMEM_F>>>(nf, ef, src, dst,
                                                We1, be1, We2, be2,
                                                Wa1, ba1, Wa2, ba2, uh_e);
    node_kernel<<<(NN + TE - 1) / TE, 128>>>(nf, Wn1, bn1, Wn2, bn2, uh_n);
}

// round 16
// speedup vs baseline: 1.9290x; 1.1594x over previous
#include <cuda_runtime.h>
#include <cuda_fp16.h>
#include <math.h>
#include <stdint.h>

// ----- problem constants -----
#define E_TOTAL 800000
#define NN      50000
#define DIN     64
#define EIN     32
#define EMIN    160
#define HID     128
#define EOUT    64
#define NMIN    128
#define DOUT    64

#define TILE    64
#define NTILES  (E_TOTAL / TILE)   // 12500
#define GRID_P  148
#define NTHR    256

// fp16 fragment tiling (edge)
#define FB      132     // b32 words per (mt,kt) fragment block (528B)
#define KT1H    10      // layer-1 k16-tiles (160/16)
#define JT2H    8       // layer-2 k16-tiles (128/16)
#define MT      4       // 64 rows / 16

// node tiling
#define NTILE    64
#define NTILES_N ((NN + NTILE - 1) / NTILE)   // 782
#define KTN      8      // 128/16

// ----- scratch -----
__device__ float g_denom[NN];
__device__ float g_agg[(size_t)NN * EOUT];

// ----- edge smem layout (bytes) -----
#define XBYTES   (MT * KT1H * FB * 4)            // 21120
#define SM_X0    0
#define SM_X1    XBYTES
#define SM_H     (2 * XBYTES)                    // 42240
#define SM_B1E   (SM_H + MT * JT2H * FB * 4)     // 59136
#define SM_B1A   (SM_B1E + KT1H * 16 * 64 * 4)   // 100096
#define SM_B2    (SM_B1A + KT1H * 16 * 64 * 4)   // 141056
#define SM_BE1   (SM_B2 + JT2H * 8 * 64 * 4)     // 157440
#define SM_BE2   (SM_BE1 + 512)
#define SM_BA1   (SM_BE2 + 256)
#define SM_WA2   (SM_BA1 + 512)
#define SM_PART  (SM_WA2 + 512)
#define SM_SEX   (SM_PART + 1024)
#define SM_SDST  (SM_SEX + 256)
#define SMEM_F   (SM_SDST + 256)                 // 161792

// ----- node smem layout (bytes) -----
#define SMN_X    0
#define SMN_H    (MT * KTN * FB * 4)             // 16896
#define SMN_B1   (2 * (MT * KTN * FB * 4))       // 33792
#define SMN_B2   (SMN_B1 + KTN * 16 * 64 * 4)    // +32768 = 66560
#define SMN_BN1  (SMN_B2 + KTN * 8 * 64 * 4)     // +16384 = 82944
#define SMN_BN2  (SMN_BN1 + 512)
#define SMEM_N   (SMN_BN2 + 256)                 // 83712

// ============================================================ helpers
__device__ __forceinline__ uint32_t pack2h(float lo, float hi) {
    __half2 h = __floats2half2_rn(lo, hi);
    return *(uint32_t*)&h;
}

__device__ __forceinline__ void mma16(float* d, const uint32_t* a, uint32_t b0, uint32_t b1) {
    asm volatile(
        "mma.sync.aligned.m16n8k16.row.col.f32.f16.f16.f32 "
        "{%0,%1,%2,%3}, {%4,%5,%6,%7}, {%8,%9}, {%0,%1,%2,%3};"
        : "+f"(d[0]), "+f"(d[1]), "+f"(d[2]), "+f"(d[3])
        : "r"(a[0]), "r"(a[1]), "r"(a[2]), "r"(a[3]), "r"(b0), "r"(b1));
}

__device__ __forceinline__ void redv2(float* p, float x, float y) {
    asm volatile("red.global.add.v2.f32 [%0], {%1, %2};"
                 :: "l"(p), "f"(x), "f"(y) : "memory");
}

// pack [K x N] row-major fp32 weight into fp16 m16n8k16 B-fragment layout.
__device__ __forceinline__ void pack_Bh(__half* fb, const float* __restrict__ W,
                                        int K, int N, int tid, int nthr)
{
    const int NPB = N >> 3;
    for (int idx = tid; idx < K * N; idx += nthr) {
        const int k = idx / N, n = idx - k * N;
        const int lane = ((n & 7) << 2) + ((k & 7) >> 1);
        const int blk  = (k >> 4) * NPB + (n >> 3);
        const int reg  = (k >> 3) & 1;
        const int pos  = k & 1;
        fb[(blk * 32 + lane) * 4 + reg * 2 + pos] = __float2half_rn(W[idx]);
    }
}

// edge gather: 4 threads/edge, 10 float4 each (into registers)
__device__ __forceinline__ void gather_ld(
    const float* __restrict__ nf, const float* __restrict__ ef,
    const int* __restrict__ src, const int* __restrict__ dst,
    int tile, int tid, float4* pv, int* pd)
{
    const int e_loc = tid >> 2, sub = tid & 3;
    const int e = tile * TILE + e_loc;
    const int s = src[e], d = dst[e];
    *pd = d;
    const float4* nfs = (const float4*)nf + (size_t)s * 16;
    const float4* nfd = (const float4*)nf + (size_t)d * 16;
    const float4* efe = (const float4*)ef + (size_t)e * 8;
    #pragma unroll
    for (int i = 0; i < 10; i++) {
        const int f = sub * 10 + i;    // 0..39
        if (f < 16)      pv[i] = __ldg(&nfs[f]);
        else if (f < 32) pv[i] = __ldg(&nfd[f - 16]);
        else             pv[i] = __ldg(&efe[f - 32]);
    }
}

__device__ __forceinline__ void gather_st(uint32_t* sxu, int* sdst, int tid,
                                          const float4* pv, int pd)
{
    const int e_loc = tid >> 2, sub = tid & 3;
    const int mt = e_loc >> 4;
    const int rr = e_loc & 15;
    const int g = rr & 7, half = rr >> 3;
    if (sub == 0) sdst[e_loc] = pd;
    #pragma unroll
    for (int i = 0; i < 10; i++) {
        const int f = sub * 10 + i;
        const int kt    = f >> 2;
        const int tg    = (f & 1) * 2;
        const int thalf = (f >> 1) & 1;
        const int base  = (mt * KT1H + kt) * FB + (g * 4 + tg) * 4 + half + 2 * thalf;
        sxu[base]     = pack2h(pv[i].x, pv[i].y);
        sxu[base + 4] = pack2h(pv[i].z, pv[i].w);
    }
}

// ============================================================
// K0: init scratch (vectorized)
// ============================================================
__global__ void init_kernel() {
    int idx = blockIdx.x * blockDim.x + threadIdx.x;   // NN*16 float4s
    ((float4*)g_agg)[idx] = make_float4(0.f, 0.f, 0.f, 0.f);
    if (idx < NN) g_denom[idx] = 0.0f;
}

// ============================================================
// K1: fused edge kernel: E-MLP + A-MLP + softmax-exp + scatter-agg
// ============================================================
__global__ __launch_bounds__(NTHR, 1) void edge_fused_kernel(
    const float* __restrict__ nf, const float* __restrict__ ef,
    const int* __restrict__ src, const int* __restrict__ dst,
    const float* __restrict__ We1, const float* __restrict__ be1,
    const float* __restrict__ We2, const float* __restrict__ be2,
    const float* __restrict__ Wa1, const float* __restrict__ ba1,
    const float* __restrict__ Wa2, const float* __restrict__ ba2,
    float* __restrict__ uh_e)
{
    extern __shared__ char smem[];
    uint32_t* sx0  = (uint32_t*)(smem + SM_X0);
    uint32_t* sx1  = (uint32_t*)(smem + SM_X1);
    uint32_t* shu  = (uint32_t*)(smem + SM_H);
    uint32_t* sB1E = (uint32_t*)(smem + SM_B1E);
    uint32_t* sB1A = (uint32_t*)(smem + SM_B1A);
    uint32_t* sB2  = (uint32_t*)(smem + SM_B2);
    float* sbe1  = (float*)(smem + SM_BE1);
    float* sbe2  = (float*)(smem + SM_BE2);
    float* sba1  = (float*)(smem + SM_BA1);
    float* swa2  = (float*)(smem + SM_WA2);
    float* spart = (float*)(smem + SM_PART);
    float* sex   = (float*)(smem + SM_SEX);
    int*   sdst  = (int*)(smem + SM_SDST);

    const int tid = threadIdx.x;
    const int w = tid >> 5, lane = tid & 31;
    const int wm = w & 1, wn = w >> 1;
    const int tig = lane & 3, gid = lane >> 2;

    pack_Bh((__half*)sB1E, We1, EMIN, HID, tid, NTHR);
    pack_Bh((__half*)sB1A, Wa1, EMIN, HID, tid, NTHR);
    pack_Bh((__half*)sB2,  We2, HID, EOUT, tid, NTHR);
    if (tid < 128) { sbe1[tid] = be1[tid]; sba1[tid] = ba1[tid]; swa2[tid] = Wa2[tid]; }
    if (tid < 64)  sbe2[tid] = be2[tid];
    const float ba2v = ba2[0];
    __syncthreads();

    float4 pv[10];
    int pd = 0;
    if (blockIdx.x < NTILES)
        gather_ld(nf, ef, src, dst, blockIdx.x, tid, pv, &pd);

    int buf = 0;
    for (int tile = blockIdx.x; tile < NTILES; tile += gridDim.x) {
        uint32_t* sxu = buf ? sx1 : sx0;

        gather_st(sxu, sdst, tid, pv, pd);
        __syncthreads();

        const int nt = tile + gridDim.x;
        if (nt < NTILES)
            gather_ld(nf, ef, src, dst, nt, tid, pv, &pd);

        // ---- layer 1 (E + A fused) ----
        float accE[2][4][4], accA[2][4][4];
        #pragma unroll
        for (int mi = 0; mi < 2; mi++)
            #pragma unroll
            for (int ni = 0; ni < 4; ni++)
                #pragma unroll
                for (int c = 0; c < 4; c++) { accE[mi][ni][c] = 0.f; accA[mi][ni][c] = 0.f; }

        #pragma unroll
        for (int kt = 0; kt < KT1H; kt++) {
            uint32_t a[2][4];
            #pragma unroll
            for (int mi = 0; mi < 2; mi++) {
                const uint4 t = *(const uint4*)&sxu[((wm * 2 + mi) * KT1H + kt) * FB + lane * 4];
                a[mi][0] = t.x; a[mi][1] = t.y; a[mi][2] = t.z; a[mi][3] = t.w;
            }
            #pragma unroll
            for (int ni = 0; ni < 4; ni++) {
                const int n8 = wn * 4 + ni;
                const uint2 bE = *(const uint2*)&sB1E[((kt * 16 + n8) * 32 + lane) * 2];
                mma16(accE[0][ni], a[0], bE.x, bE.y);
                mma16(accE[1][ni], a[1], bE.x, bE.y);
                const uint2 bA = *(const uint2*)&sB1A[((kt * 16 + n8) * 32 + lane) * 2];
                mma16(accA[0][ni], a[0], bA.x, bA.y);
                mma16(accA[1][ni], a[1], bA.x, bA.y);
            }
        }

        // ---- epilogue E: relu+bias -> h fragments ----
        #pragma unroll
        for (int mi = 0; mi < 2; mi++) {
            const int mt = wm * 2 + mi;
            #pragma unroll
            for (int ni = 0; ni < 4; ni++) {
                const int j0 = wn * 32 + ni * 8 + 2 * tig;
                const int jt = wn * 2 + (ni >> 1);
                const int thalf = ni & 1;
                const float b0 = sbe1[j0], b1 = sbe1[j0 + 1];
                const int base = (mt * JT2H + jt) * FB + (gid * 4 + tig) * 4 + 2 * thalf;
                shu[base]     = pack2h(fmaxf(accE[mi][ni][0] + b0, 0.f),
                                       fmaxf(accE[mi][ni][1] + b1, 0.f));
                shu[base + 1] = pack2h(fmaxf(accE[mi][ni][2] + b0, 0.f),
                                       fmaxf(accE[mi][ni][3] + b1, 0.f));
            }
        }

        // ---- epilogue A: logit partials ----
        #pragma unroll
        for (int mi = 0; mi < 2; mi++) {
            const int mt = wm * 2 + mi;
            float part[2] = {0.f, 0.f};
            #pragma unroll
            for (int ni = 0; ni < 4; ni++) {
                const int j0 = wn * 32 + ni * 8 + 2 * tig;
                const float w0 = swa2[j0], w1 = swa2[j0 + 1];
                const float b0 = sba1[j0], b1 = sba1[j0 + 1];
                part[0] += fmaxf(accA[mi][ni][0] + b0, 0.f) * w0
                         + fmaxf(accA[mi][ni][1] + b1, 0.f) * w1;
                part[1] += fmaxf(accA[mi][ni][2] + b0, 0.f) * w0
                         + fmaxf(accA[mi][ni][3] + b1, 0.f) * w1;
            }
            #pragma unroll
            for (int h2 = 0; h2 < 2; h2++) {
                float v = part[h2];
                v += __shfl_xor_sync(0xffffffff, v, 1);
                v += __shfl_xor_sync(0xffffffff, v, 2);
                if (tig == 0)
                    spart[wn * 64 + mt * 16 + h2 * 8 + gid] = v;
            }
        }
        __syncthreads();

        // ---- softmax exp (max-free) + denom scatter ----
        if (tid < TILE) {
            const float logit = spart[tid] + spart[64 + tid]
                              + spart[128 + tid] + spart[192 + tid] + ba2v;
            const float ex = expf(logit);
            sex[tid] = ex;
            atomicAdd(&g_denom[sdst[tid]], ex);
        }
        __syncthreads();

        // ---- layer 2 (E) ----
        float acc2[2][2][4];
        #pragma unroll
        for (int mi = 0; mi < 2; mi++)
            #pragma unroll
            for (int ni = 0; ni < 2; ni++)
                #pragma unroll
                for (int c = 0; c < 4; c++) acc2[mi][ni][c] = 0.f;

        #pragma unroll
        for (int jt = 0; jt < JT2H; jt++) {
            uint32_t a[2][4];
            #pragma unroll
            for (int mi = 0; mi < 2; mi++) {
                const uint4 t = *(const uint4*)&shu[((wm * 2 + mi) * JT2H + jt) * FB + lane * 4];
                a[mi][0] = t.x; a[mi][1] = t.y; a[mi][2] = t.z; a[mi][3] = t.w;
            }
            #pragma unroll
            for (int ni = 0; ni < 2; ni++) {
                const int n8 = wn * 2 + ni;
                const uint2 b = *(const uint2*)&sB2[((jt * 8 + n8) * 32 + lane) * 2];
                mma16(acc2[0][ni], a[0], b.x, b.y);
                mma16(acc2[1][ni], a[1], b.x, b.y);
            }
        }

        // ---- store uh_e + scatter exp-weighted aggregation ----
        #pragma unroll
        for (int mi = 0; mi < 2; mi++) {
            const int le0 = (wm * 2 + mi) * 16 + gid;
            const int e0  = tile * TILE + le0;
            const float w0x = sex[le0];
            const float w1x = sex[le0 + 8];
            const int d0 = sdst[le0];
            const int d1 = sdst[le0 + 8];
            #pragma unroll
            for (int ni = 0; ni < 2; ni++) {
                const int o = wn * 16 + ni * 8 + 2 * tig;
                const float b0 = sbe2[o], b1 = sbe2[o + 1];
                float2 v0, v1;
                v0.x = acc2[mi][ni][0] + b0; v0.y = acc2[mi][ni][1] + b1;
                v1.x = acc2[mi][ni][2] + b0; v1.y = acc2[mi][ni][3] + b1;
                *(float2*)&uh_e[(size_t)e0 * EOUT + o] = v0;
                *(float2*)&uh_e[(size_t)(e0 + 8) * EOUT + o] = v1;
                redv2(&g_agg[(size_t)d0 * EOUT + o], v0.x * w0x, v0.y * w0x);
                redv2(&g_agg[(size_t)d1 * EOUT + o], v1.x * w1x, v1.y * w1x);
            }
        }
        buf ^= 1;
    }
}

// ============================================================
// K2: node MLP on concat(agg/denom, nf), fp16 mma, persistent
// ============================================================
__global__ __launch_bounds__(NTHR, 1) void node_tc_kernel(
    const float* __restrict__ nf,
    const float* __restrict__ Wn1, const float* __restrict__ bn1,
    const float* __restrict__ Wn2, const float* __restrict__ bn2,
    float* __restrict__ uh_n)
{
    extern __shared__ char smem[];
    uint32_t* sxu = (uint32_t*)(smem + SMN_X);
    uint32_t* shu = (uint32_t*)(smem + SMN_H);
    uint32_t* sB1 = (uint32_t*)(smem + SMN_B1);
    uint32_t* sB2 = (uint32_t*)(smem + SMN_B2);
    float* sbn1 = (float*)(smem + SMN_BN1);
    float* sbn2 = (float*)(smem + SMN_BN2);

    const int tid = threadIdx.x;
    const int w = tid >> 5, lane = tid & 31;
    const int wm = w & 1, wn = w >> 1;
    const int tig = lane & 3, gid = lane >> 2;

    pack_Bh((__half*)sB1, Wn1, NMIN, HID, tid, NTHR);
    pack_Bh((__half*)sB2, Wn2, HID, DOUT, tid, NTHR);
    if (tid < 128) sbn1[tid] = bn1[tid];
    if (tid < 64)  sbn2[tid] = bn2[tid];
    __syncthreads();

    for (int tile = blockIdx.x; tile < NTILES_N; tile += gridDim.x) {
        __syncthreads();

        // ---- gather concat(agg*rden, nf) into fragments ----
        {
            const int e_loc = tid >> 2, sub = tid & 3;
            const int n = tile * NTILE + e_loc;
            const bool ok = (n < NN);
            const int mt = e_loc >> 4;
            const int rr = e_loc & 15;
            const int g = rr & 7, half = rr >> 3;
            const float rden = ok ? (1.0f / fmaxf(g_denom[n], 1e-38f)) : 0.0f;
            const float4* ag4 = (const float4*)g_agg + (size_t)(ok ? n : 0) * 16;
            const float4* nf4 = (const float4*)nf + (size_t)(ok ? n : 0) * 16;
            #pragma unroll
            for (int i = 0; i < 8; i++) {
                const int f = sub * 8 + i;    // 0..31
                float4 v = make_float4(0.f, 0.f, 0.f, 0.f);
                if (ok) {
                    if (f < 16) {
                        v = __ldg(&ag4[f]);
                        v.x *= rden; v.y *= rden; v.z *= rden; v.w *= rden;
                    } else {
                        v = __ldg(&nf4[f - 16]);
                    }
                }
                const int kt    = f >> 2;
                const int tg    = (f & 1) * 2;
                const int thalf = (f >> 1) & 1;
                const int base  = (mt * KTN + kt) * FB + (g * 4 + tg) * 4 + half + 2 * thalf;
                sxu[base]     = pack2h(v.x, v.y);
                sxu[base + 4] = pack2h(v.z, v.w);
            }
        }
        __syncthreads();

        // ---- layer 1: [64n x 128k] x [128k x 128n] ----
        float acc[2][4][4];
        #pragma unroll
        for (int mi = 0; mi < 2; mi++)
            #pragma unroll
            for (int ni = 0; ni < 4; ni++)
                #pragma unroll
                for (int c = 0; c < 4; c++) acc[mi][ni][c] = 0.f;

        #pragma unroll
        for (int kt = 0; kt < KTN; kt++) {
            uint32_t a[2][4];
            #pragma unroll
            for (int mi = 0; mi < 2; mi++) {
                const uint4 t = *(const uint4*)&sxu[((wm * 2 + mi) * KTN + kt) * FB + lane * 4];
                a[mi][0] = t.x; a[mi][1] = t.y; a[mi][2] = t.z; a[mi][3] = t.w;
            }
            #pragma unroll
            for (int ni = 0; ni < 4; ni++) {
                const int n8 = wn * 4 + ni;
                const uint2 b = *(const uint2*)&sB1[((kt * 16 + n8) * 32 + lane) * 2];
                mma16(acc[0][ni], a[0], b.x, b.y);
                mma16(acc[1][ni], a[1], b.x, b.y);
            }
        }

        // ---- epilogue: relu+bias -> h fragments ----
        #pragma unroll
        for (int mi = 0; mi < 2; mi++) {
            const int mt = wm * 2 + mi;
            #pragma unroll
            for (int ni = 0; ni < 4; ni++) {
                const int j0 = wn * 32 + ni * 8 + 2 * tig;
                const int jt = wn * 2 + (ni >> 1);
                const int thalf = ni & 1;
                const float b0 = sbn1[j0], b1 = sbn1[j0 + 1];
                const int base = (mt * KTN + jt) * FB + (gid * 4 + tig) * 4 + 2 * thalf;
                shu[base]     = pack2h(fmaxf(acc[mi][ni][0] + b0, 0.f),
                                       fmaxf(acc[mi][ni][1] + b1, 0.f));
                shu[base + 1] = pack2h(fmaxf(acc[mi][ni][2] + b0, 0.f),
                                       fmaxf(acc[mi][ni][3] + b1, 0.f));
            }
        }
        __syncthreads();

        // ---- layer 2: [64n x 128k] x [128k x 64n] ----
        float acc2[2][2][4];
        #pragma unroll
        for (int mi = 0; mi < 2; mi++)
            #pragma unroll
            for (int ni = 0; ni < 2; ni++)
                #pragma unroll
                for (int c = 0; c < 4; c++) acc2[mi][ni][c] = 0.f;

        #pragma unroll
        for (int jt = 0; jt < KTN; jt++) {
            uint32_t a[2][4];
            #pragma unroll
            for (int mi = 0; mi < 2; mi++) {
                const uint4 t = *(const uint4*)&shu[((wm * 2 + mi) * KTN + jt) * FB + lane * 4];
                a[mi][0] = t.x; a[mi][1] = t.y; a[mi][2] = t.z; a[mi][3] = t.w;
            }
            #pragma unroll
            for (int ni = 0; ni < 2; ni++) {
                const int n8 = wn * 2 + ni;
                const uint2 b = *(const uint2*)&sB2[((jt * 8 + n8) * 32 + lane) * 2];
                mma16(acc2[0][ni], a[0], b.x, b.y);
                mma16(acc2[1][ni], a[1], b.x, b.y);
            }
        }

        // ---- store uh_n (bounds-guarded) ----
        #pragma unroll
        for (int mi = 0; mi < 2; mi++) {
            const int n0 = tile * NTILE + (wm * 2 + mi) * 16 + gid;
            #pragma unroll
            for (int ni = 0; ni < 2; ni++) {
                const int o = wn * 16 + ni * 8 + 2 * tig;
                const float b0 = sbn2[o], b1 = sbn2[o + 1];
                if (n0 < NN) {
                    float2 v; v.x = acc2[mi][ni][0] + b0; v.y = acc2[mi][ni][1] + b1;
                    *(float2*)&uh_n[(size_t)n0 * DOUT + o] = v;
                }
                if (n0 + 8 < NN) {
                    float2 v; v.x = acc2[mi][ni][2] + b0; v.y = acc2[mi][ni][3] + b1;
                    *(float2*)&uh_n[(size_t)(n0 + 8) * DOUT + o] = v;
                }
            }
        }
    }
}

// ============================================================
extern "C" void kernel_launch(void* const* d_in, const int* in_sizes, int n_in,
                              void* d_out, int out_size) {
    const float* nf  = (const float*)d_in[0];
    const float* ef  = (const float*)d_in[1];
    const int*   src = (const int*)d_in[2];
    const int*   dst = (const int*)d_in[3];
    const float* We1 = (const float*)d_in[4];
    const float* be1 = (const float*)d_in[5];
    const float* We2 = (const float*)d_in[6];
    const float* be2 = (const float*)d_in[7];
    const float* Wa1 = (const float*)d_in[8];
    const float* ba1 = (const float*)d_in[9];
    const float* Wa2 = (const float*)d_in[10];
    const float* ba2 = (const float*)d_in[11];
    const float* Wn1 = (const float*)d_in[12];
    const float* bn1 = (const float*)d_in[13];
    const float* Wn2 = (const float*)d_in[14];
    const float* bn2 = (const float*)d_in[15];

    float* out  = (float*)d_out;
    float* uh_n = out;
    float* uh_e = out + (size_t)NN * DOUT;

    static bool attr_set = false;
    if (!attr_set) {
        cudaFuncSetAttribute(edge_fused_kernel,
                             cudaFuncAttributeMaxDynamicSharedMemorySize, SMEM_F);
        cudaFuncSetAttribute(node_tc_kernel,
                             cudaFuncAttributeMaxDynamicSharedMemorySize, SMEM_N);
        attr_set = true;
    }

    init_kernel<<<(NN * 16) / 256, 256>>>();
    edge_fused_kernel<<<GRID_P, NTHR, SMEM_F>>>(nf, ef, src, dst,
                                                We1, be1, We2, be2,
                                                Wa1, ba1, Wa2, ba2, uh_e);
    node_tc_kernel<<<GRID_P, NTHR, SMEM_N>>>(nf, Wn1, bn1, Wn2, bn2, uh_n);
}